// round 3
// baseline (speedup 1.0000x reference)
#include <cuda_runtime.h>
#include <cmath>
#include <cstddef>

// ---------------------------------------------------------------------------
// Problem constants
// ---------------------------------------------------------------------------
#define G_      64
#define S_      32
#define P_      8
#define D_IN_   768
#define D_H_    256
#define HEADS_  4
#define D_FF_   2048
#define NH_T_   4
#define HD_     64          // D_H / NH_T
#define B_      512         // G*P sequences
#define MAXT_   32          // max transformer sequence length (j+1, j<=31)
#define MAXNT_  (B_*MAXT_)  // 16384 tokens max

// ---------------------------------------------------------------------------
// Scratch pool (static __device__: no allocation allowed in kernel_launch)
// ---------------------------------------------------------------------------
// float offsets into the pool
#define OFF_H      0u                          // [16384*256]  hidden states
#define OFF_TMPA   4194304u                    // [16384*768]  qkv / 256-wide tmp
#define OFF_FFB    16777216u                   // [16384*2048] ff intermediate / tmp
#define OFF_AO     50331648u                   // [16384*256]  attention output
#define OFF_MEM    54525952u                   // [32*512*256] per-step GAT outputs
#define OFF_XJ     58720256u                   // [512*768]
#define OFF_POOLED 59113472u                   // [512*768]
#define OFF_HG     59506688u                   // [512*1024]
#define OFF_SC     60030976u                   // [64*1536]
#define OFF_SPK    60129280u                   // [64*768]
#define OFF_CATT   60178432u                   // [512*256]
#define OFF_CH     60309504u                   // [512*256]
#define OFF_CT1    60440576u                   // [512*2048]
#define OFF_CT2    61489152u                   // [512*256]
#define POOL_SZ    61620224u

__device__ float g_pool[POOL_SZ];

// ---------------------------------------------------------------------------
// Generic SGEMM:  C[m,n] = sum_k A[m,k]*B[n,k] + bias[n]  (optional ReLU)
// A: MxK row-major, B: NxK row-major (i.e. computes A @ B^T).
// 128x128 tile, BK=8, 256 threads, 8x8 per thread, float4 global loads.
// ---------------------------------------------------------------------------
__global__ __launch_bounds__(256) void sgemm_nt(
    const float* __restrict__ A, const float* __restrict__ B,
    float* __restrict__ C, const float* __restrict__ bias,
    int M, int N, int K, int doRelu)
{
    __shared__ float As[8][128];
    __shared__ float Bs[8][128];

    const int tid = threadIdx.x;
    const int tx  = tid & 15;       // n direction (8 cols each)
    const int ty  = tid >> 4;       // m direction (8 rows each)
    const int m0  = blockIdx.y * 128;
    const int n0  = blockIdx.x * 128;

    const int lrow = tid >> 1;      // 0..127
    const int lk4  = (tid & 1) * 4; // 0 or 4

    const bool aValid = (m0 + lrow) < M;
    const bool bValid = (n0 + lrow) < N;
    const float* Aptr = A + (size_t)(aValid ? (m0 + lrow) : 0) * K + lk4;
    const float* Bptr = B + (size_t)(bValid ? (n0 + lrow) : 0) * K + lk4;

    float acc[8][8];
#pragma unroll
    for (int i = 0; i < 8; i++)
#pragma unroll
        for (int j = 0; j < 8; j++) acc[i][j] = 0.f;

    for (int kt = 0; kt < K; kt += 8) {
        float4 a4 = aValid ? *(const float4*)(Aptr + kt) : make_float4(0.f,0.f,0.f,0.f);
        float4 b4 = bValid ? *(const float4*)(Bptr + kt) : make_float4(0.f,0.f,0.f,0.f);
        As[lk4+0][lrow] = a4.x; As[lk4+1][lrow] = a4.y;
        As[lk4+2][lrow] = a4.z; As[lk4+3][lrow] = a4.w;
        Bs[lk4+0][lrow] = b4.x; Bs[lk4+1][lrow] = b4.y;
        Bs[lk4+2][lrow] = b4.z; Bs[lk4+3][lrow] = b4.w;
        __syncthreads();
#pragma unroll
        for (int k = 0; k < 8; k++) {
            float a[8], b[8];
            *(float4*)&a[0] = *(const float4*)&As[k][ty*8];
            *(float4*)&a[4] = *(const float4*)&As[k][ty*8+4];
            *(float4*)&b[0] = *(const float4*)&Bs[k][tx*8];
            *(float4*)&b[4] = *(const float4*)&Bs[k][tx*8+4];
#pragma unroll
            for (int i = 0; i < 8; i++)
#pragma unroll
                for (int j = 0; j < 8; j++)
                    acc[i][j] += a[i]*b[j];
        }
        __syncthreads();
    }

    float bv[8];
#pragma unroll
    for (int j = 0; j < 8; j++) {
        int n = n0 + tx*8 + j;
        bv[j] = (bias != nullptr && n < N) ? bias[n] : 0.f;
    }
#pragma unroll
    for (int i = 0; i < 8; i++) {
        int m = m0 + ty*8 + i;
        if (m < M) {
            float* Crow = C + (size_t)m * N + n0 + tx*8;
#pragma unroll
            for (int j = 0; j < 8; j++) {
                int n = n0 + tx*8 + j;
                if (n < N) {
                    float v = acc[i][j] + bv[j];
                    if (doRelu) v = fmaxf(v, 0.f);
                    Crow[j] = v;
                }
            }
        }
    }
}

// ---------------------------------------------------------------------------
// Build transformer input: H[(b*T+t)*256+d] = t < T-1 ? MEM[t][b][d] : 0
// ---------------------------------------------------------------------------
__global__ void build_h0(float* __restrict__ H, const float* __restrict__ MEMB, int T)
{
    size_t i = (size_t)blockIdx.x * 256 + threadIdx.x;
    size_t total = (size_t)B_ * T * D_H_;
    if (i >= total) return;
    int d = (int)(i & 255);
    size_t bt = i >> 8;
    int t = (int)(bt % T);
    int b = (int)(bt / T);
    H[i] = (t < T-1) ? MEMB[((size_t)t * B_ + b) * D_H_ + d] : 0.f;
}

// ---------------------------------------------------------------------------
// Fused attention. One block per (b, head). 128 threads (4 warps).
// T <= 32 so one score per lane. lastOnly: only query t = T-1, compact output.
// ---------------------------------------------------------------------------
__device__ __forceinline__ void attn_one(
    const float* __restrict__ base, const float* __restrict__ Kt,
    const float* __restrict__ Vs, float* __restrict__ Qrow,
    int T, int h, int lane, int t, float* __restrict__ op)
{
    Qrow[lane]      = base[(size_t)t*768 + h*64 + lane];
    Qrow[lane + 32] = base[(size_t)t*768 + h*64 + 32 + lane];
    __syncwarp();
    float sc;
    if (lane < T) {
        float s = 0.f;
#pragma unroll
        for (int d = 0; d < 64; d++) s += Qrow[d] * Kt[d*33 + lane];
        sc = s * 0.125f;   // 1/sqrt(64)
    } else {
        sc = -3.4e38f;
    }
    float m = sc;
#pragma unroll
    for (int o = 16; o > 0; o >>= 1) m = fmaxf(m, __shfl_xor_sync(0xffffffffu, m, o));
    float p = expf(sc - m);
    float sum = p;
#pragma unroll
    for (int o = 16; o > 0; o >>= 1) sum += __shfl_xor_sync(0xffffffffu, sum, o);
    float inv = 1.f / sum;
    float o0 = 0.f, o1 = 0.f;
    for (int s = 0; s < T; s++) {
        float ps = __shfl_sync(0xffffffffu, p, s);
        o0 += ps * Vs[s*64 + lane];
        o1 += ps * Vs[s*64 + 32 + lane];
    }
    op[lane]      = o0 * inv;
    op[lane + 32] = o1 * inv;
    __syncwarp();
}

__global__ __launch_bounds__(128) void attn_kernel(
    const float* __restrict__ QKV, float* __restrict__ out, int T, int lastOnly)
{
    int blk = blockIdx.x;
    int b = blk >> 2, h = blk & 3;
    int tid = threadIdx.x, lane = tid & 31, w = tid >> 5;

    __shared__ float Kt[64*33];       // Kt[d*33 + s]
    __shared__ float Vs[32*64];       // Vs[s*64 + d]
    __shared__ float Qs[4][64];

    const float* base = QKV + (size_t)b * T * 768;
    for (int idx = tid; idx < T*64; idx += 128) {
        int s = idx >> 6, d = idx & 63;
        Kt[d*33 + s] = base[(size_t)s*768 + 256 + h*64 + d];
        Vs[s*64 + d] = base[(size_t)s*768 + 512 + h*64 + d];
    }
    __syncthreads();

    if (lastOnly) {
        if (w == 0) {
            float* op = out + (size_t)b * D_H_ + h*64;
            attn_one(base, Kt, Vs, Qs[0], T, h, lane, T-1, op);
        }
    } else {
        for (int t = w; t < T; t += 4) {
            float* op = out + ((size_t)b * T + t) * D_H_ + h*64;
            attn_one(base, Kt, Vs, Qs[w], T, h, lane, t, op);
        }
    }
}

// ---------------------------------------------------------------------------
// Fused residual add + LayerNorm over 256 features. One block (256 thr) / row.
// dst[row] = LN(resid[row*rStride + rOff] + delta[row])
// ---------------------------------------------------------------------------
__global__ __launch_bounds__(256) void add_ln(
    float* __restrict__ dst, const float* __restrict__ resid,
    const float* __restrict__ delta,
    const float* __restrict__ gamma, const float* __restrict__ beta,
    int rStride, int rOff)
{
    int row = blockIdx.x;
    int d = threadIdx.x;
    const float* rrow = resid + ((size_t)row * rStride + rOff) * D_H_;
    float v = rrow[d] + delta[(size_t)row * D_H_ + d];

    __shared__ float s1[8], s2[8];
    float sum = v, sq = v*v;
#pragma unroll
    for (int o = 16; o > 0; o >>= 1) {
        sum += __shfl_down_sync(0xffffffffu, sum, o);
        sq  += __shfl_down_sync(0xffffffffu, sq,  o);
    }
    int wrp = d >> 5, lane = d & 31;
    if (lane == 0) { s1[wrp] = sum; s2[wrp] = sq; }
    __syncthreads();
    if (wrp == 0) {
        float a = (lane < 8) ? s1[lane] : 0.f;
        float c = (lane < 8) ? s2[lane] : 0.f;
#pragma unroll
        for (int o = 4; o > 0; o >>= 1) {
            a += __shfl_down_sync(0xffffffffu, a, o);
            c += __shfl_down_sync(0xffffffffu, c, o);
        }
        if (lane == 0) { s1[0] = a; s2[0] = c; }
    }
    __syncthreads();
    float mean = s1[0] * (1.f/256.f);
    float var  = s2[0] * (1.f/256.f) - mean*mean;
    float r = rsqrtf(var + 1e-5f);
    dst[(size_t)row * D_H_ + d] = (v - mean) * r * gamma[d] + beta[d];
}

// ---------------------------------------------------------------------------
// spk_cat builder: SC[g][0:768] = POOLED[g*8], SC[g][768:1536] = x[(g*32+j)*8]
// ---------------------------------------------------------------------------
__global__ void build_spkcat(float* __restrict__ SC, const float* __restrict__ POOLED,
                             const float* __restrict__ x, int j)
{
    int i = blockIdx.x * 256 + threadIdx.x;
    if (i >= 64 * 1536) return;
    int g = i / 1536, c = i % 1536;
    SC[i] = (c < 768) ? POOLED[(size_t)(g*8) * 768 + c]
                      : x[(size_t)((g*32 + j) * 8) * 768 + (c - 768)];
}

// ---------------------------------------------------------------------------
// XJ builder. first: XJ = x slice for step j. else: pooled with row0 <- spk.
// ---------------------------------------------------------------------------
__global__ void build_xj(float* __restrict__ XJ, const float* __restrict__ POOLED,
                         const float* __restrict__ SPK, const float* __restrict__ x,
                         int j, int first)
{
    int i = blockIdx.x * 256 + threadIdx.x;
    if (i >= B_ * 768) return;
    int b = i / 768, c = i % 768;
    int g = b >> 3, p = b & 7;
    float v;
    if (first)       v = x[(size_t)((g*32 + j) * 8 + p) * 768 + c];
    else if (p == 0) v = SPK[(size_t)g * 768 + c];
    else             v = POOLED[(size_t)b * 768 + c];
    XJ[i] = v;
}

// ---------------------------------------------------------------------------
// GAT epilogue (after HG = XJ @ gat_w^T, [512,1024] = [512][head*256+o]).
// One block per group g. adj: node d attends {0, d} (d>0), node 0 -> {0}.
// ---------------------------------------------------------------------------
__global__ __launch_bounds__(256) void gat_finish(
    float* __restrict__ MEMj, const float* __restrict__ HG,
    const float* __restrict__ a_src, const float* __restrict__ a_dst,
    const float* __restrict__ gat_b)
{
    int g = blockIdx.x;
    int tid = threadIdx.x, lane = tid & 31, w = tid >> 5; // 8 warps -> p = w
    __shared__ float sES[8][4], sED[8][4];
    const float* hgBase = HG + (size_t)g * 8 * 1024;

    {
        int p = w;
        const float* hp = hgBase + (size_t)p * 1024;
        for (int h = 0; h < 4; h++) {
            float s1 = 0.f, s2 = 0.f;
            const float* hr  = hp + h*256;
            const float* asr = a_src + h*256;
            const float* adr = a_dst + h*256;
            for (int d = lane; d < 256; d += 32) {
                float hv = hr[d];
                s1 += hv * asr[d];
                s2 += hv * adr[d];
            }
#pragma unroll
            for (int o = 16; o > 0; o >>= 1) {
                s1 += __shfl_down_sync(0xffffffffu, s1, o);
                s2 += __shfl_down_sync(0xffffffffu, s2, o);
            }
            if (lane == 0) { sES[p][h] = s1; sED[p][h] = s2; }
        }
    }
    __syncthreads();

    int o = tid;  // feature 0..255
    for (int d = 0; d < 8; d++) {
        float val = 0.f;
        if (d == 0) {
#pragma unroll
            for (int h = 0; h < 4; h++)
                val += hgBase[h*256 + o];                // alpha = 1 on s=0
        } else {
#pragma unroll
            for (int h = 0; h < 4; h++) {
                float e0 = sES[0][h] + sED[d][h];
                float e1 = sES[d][h] + sED[d][h];
                e0 = (e0 > 0.f) ? e0 : 0.2f*e0;          // leaky_relu 0.2
                e1 = (e1 > 0.f) ? e1 : 0.2f*e1;
                float m  = fmaxf(e0, e1);
                float w0 = expf(e0 - m), w1 = expf(e1 - m);
                float inv = 1.f / (w0 + w1);
                val += (w0 * hgBase[h*256 + o] +
                        w1 * hgBase[(size_t)d*1024 + h*256 + o]) * inv;
            }
        }
        MEMj[(size_t)(g*8 + d) * D_H_ + o] = 0.25f * val + gat_b[o];
    }
}

// ---------------------------------------------------------------------------
// Final classifier: out[(g*32+s)*7+c] = MEM[s][g*8] . cls_w[c] + cls_b[c]
// ---------------------------------------------------------------------------
__global__ __launch_bounds__(32) void cls_out(
    float* __restrict__ out, const float* __restrict__ MEMB,
    const float* __restrict__ w, const float* __restrict__ bias)
{
    int r = blockIdx.x;                // 0..2047
    int lane = threadIdx.x;
    int g = r >> 5, s = r & 31;
    const float* v = MEMB + ((size_t)s * B_ + g*8) * D_H_;
    for (int c = 0; c < 7; c++) {
        float sum = 0.f;
        for (int d = lane; d < 256; d += 32) sum += v[d] * w[c*256 + d];
#pragma unroll
        for (int o = 16; o > 0; o >>= 1) sum += __shfl_down_sync(0xffffffffu, sum, o);
        if (lane == 0) out[(size_t)r*7 + c] = sum + bias[c];
    }
}

// ---------------------------------------------------------------------------
// Host orchestration
// ---------------------------------------------------------------------------
static inline void gemm(float* C, const float* A, const float* Bw, const float* bias,
                        int M, int N, int K, int relu)
{
    dim3 grid((N + 127) / 128, (M + 127) / 128);
    sgemm_nt<<<grid, 256>>>(A, Bw, C, bias, M, N, K, relu);
}

extern "C" void kernel_launch(void* const* d_in, const int* in_sizes, int n_in,
                              void* d_out, int out_size)
{
    (void)in_sizes; (void)n_in; (void)out_size;

    const float* x      = (const float*)d_in[0];
    const float* gat_w  = (const float*)d_in[3];
    const float* a_src  = (const float*)d_in[4];
    const float* a_dst  = (const float*)d_in[5];
    const float* gat_b  = (const float*)d_in[6];
    const float* qkv_w  = (const float*)d_in[7];
    const float* qkv_b  = (const float*)d_in[8];
    const float* out_w  = (const float*)d_in[9];
    const float* out_b  = (const float*)d_in[10];
    const float* ln1_g  = (const float*)d_in[11];
    const float* ln1_b  = (const float*)d_in[12];
    const float* ff1_w  = (const float*)d_in[13];
    const float* ff1_b  = (const float*)d_in[14];
    const float* ff2_w  = (const float*)d_in[15];
    const float* ff2_b  = (const float*)d_in[16];
    const float* ln2_g  = (const float*)d_in[17];
    const float* ln2_b  = (const float*)d_in[18];
    const float* proj_w = (const float*)d_in[19];
    const float* proj_b = (const float*)d_in[20];
    const float* spk_w  = (const float*)d_in[21];
    const float* spk_b  = (const float*)d_in[22];
    const float* cls_w  = (const float*)d_in[23];
    const float* cls_b  = (const float*)d_in[24];

    float* pool = nullptr;
    cudaGetSymbolAddress((void**)&pool, g_pool);

    float* H      = pool + OFF_H;
    float* TMPA   = pool + OFF_TMPA;
    float* FFB    = pool + OFF_FFB;
    float* AO     = pool + OFF_AO;
    float* MEMB   = pool + OFF_MEM;
    float* XJ     = pool + OFF_XJ;
    float* POOLED = pool + OFF_POOLED;
    float* HG     = pool + OFF_HG;
    float* SC     = pool + OFF_SC;
    float* SPK    = pool + OFF_SPK;
    float* C_ATT  = pool + OFF_CATT;
    float* C_H    = pool + OFF_CH;
    float* C_T1   = pool + OFF_CT1;
    float* C_T2   = pool + OFF_CT2;

    for (int j = 0; j < S_; j++) {
        if (j > 0) {
            const int T  = j + 1;
            const int NT = B_ * T;

            build_h0<<<(NT*256 + 255)/256, 256>>>(H, MEMB, T);

            // ---- layer 0 (all tokens) ----
            gemm(TMPA, H, qkv_w + 0*768*256, qkv_b + 0*768, NT, 768, 256, 0);
            attn_kernel<<<B_*NH_T_, 128>>>(TMPA, AO, T, 0);
            gemm(FFB, AO, out_w + 0*256*256, out_b + 0*256, NT, 256, 256, 0);
            add_ln<<<NT, 256>>>(H, H, FFB, ln1_g + 0*256, ln1_b + 0*256, 1, 0);
            gemm(FFB, H, ff1_w + 0*2048*256, ff1_b + 0*2048, NT, 2048, 256, 1);
            gemm(TMPA, FFB, ff2_w + 0*256*2048, ff2_b + 0*256, NT, 256, 2048, 0);
            add_ln<<<NT, 256>>>(H, H, TMPA, ln2_g + 0*256, ln2_b + 0*256, 1, 0);

            // ---- layer 1 (K/V all tokens; epilogue last-token only) ----
            gemm(TMPA, H, qkv_w + 1*768*256, qkv_b + 1*768, NT, 768, 256, 0);
            attn_kernel<<<B_*NH_T_, 128>>>(TMPA, C_ATT, T, 1);
            gemm(C_T1, C_ATT, out_w + 1*256*256, out_b + 1*256, B_, 256, 256, 0);
            add_ln<<<B_, 256>>>(C_H, H, C_T1, ln1_g + 1*256, ln1_b + 1*256, T, T-1);
            gemm(C_T1, C_H, ff1_w + 1*2048*256, ff1_b + 1*2048, B_, 2048, 256, 1);
            gemm(C_T2, C_T1, ff2_w + 1*256*2048, ff2_b + 1*256, B_, 256, 2048, 0);
            add_ln<<<B_, 256>>>(C_H, C_H, C_T2, ln2_g + 1*256, ln2_b + 1*256, 1, 0);

            // ---- pooled projection + speaker path ----
            gemm(POOLED, C_H, proj_w, proj_b, B_, 768, 256, 0);
            build_spkcat<<<(64*1536 + 255)/256, 256>>>(SC, POOLED, x, j);
            gemm(SPK, SC, spk_w, spk_b, 64, 768, 1536, 1);
            build_xj<<<(B_*768 + 255)/256, 256>>>(XJ, POOLED, SPK, x, j, 0);
        } else {
            build_xj<<<(B_*768 + 255)/256, 256>>>(XJ, POOLED, SPK, x, 0, 1);
        }

        // ---- GAT ----
        gemm(HG, XJ, gat_w, nullptr, B_, 1024, 768, 0);
        gat_finish<<<G_, 256>>>(MEMB + (size_t)j * B_ * D_H_, HG, a_src, a_dst, gat_b);
    }

    cls_out<<<G_*S_, 32>>>((float*)d_out, MEMB, cls_w, cls_b);
}

// round 5
// speedup vs baseline: 2.2154x; 2.2154x over previous
#include <cuda_runtime.h>
#include <cmath>
#include <cstddef>
#include <cstdint>

// ---------------------------------------------------------------------------
// Problem constants
// ---------------------------------------------------------------------------
#define G_      64
#define S_      32
#define P_      8
#define D_IN_   768
#define D_H_    256
#define HEADS_  4
#define D_FF_   2048
#define NH_T_   4
#define B_      512         // G*P sequences
#define MAXT_   32
#define MAXNT_  (B_*MAXT_)  // 16384 tokens max

// ---------------------------------------------------------------------------
// Scratch pool (static __device__; no allocation allowed)
// ---------------------------------------------------------------------------
#define OFF_QKV0   0u                                  // [32][512][768] cached L0 qkv
#define OFF_H      (OFF_QKV0 + 32u*512u*768u)          // [16384][256]
#define OFF_AO     (OFF_H    + 16384u*256u)            // [16384][256]
#define OFF_FFB    (OFF_AO   + 16384u*256u)            // [16384][2048]
#define OFF_T256   (OFF_FFB  + 16384u*2048u)           // [16384][256]
#define OFF_KVB    (OFF_T256 + 16384u*256u)            // [16384][512]
#define OFF_MEM    (OFF_KVB  + 16384u*512u)            // [32][512][256]
#define OFF_QL     (OFF_MEM  + 32u*512u*256u)          // [512][256]
#define OFF_XJ     (OFF_QL   + 512u*256u)              // [512][768]
#define OFF_POOLED (OFF_XJ   + 512u*768u)              // [512][768]
#define OFF_HG     (OFF_POOLED + 512u*768u)            // [512][1024]
#define OFF_SC     (OFF_HG   + 512u*1024u)             // [64][1536]
#define OFF_SPK    (OFF_SC   + 64u*1536u)              // [64][768]
#define OFF_CATT   (OFF_SPK  + 64u*768u)               // [512][256]
#define OFF_CH     (OFF_CATT + 512u*256u)              // [512][256]
#define OFF_CT1    (OFF_CH   + 512u*256u)              // [512][2048]
#define OFF_CT2    (OFF_CT1  + 512u*2048u)             // [512][256]
#define POOL_SZ    (OFF_CT2  + 512u*256u)

__device__ float g_pool[POOL_SZ];

// ---------------------------------------------------------------------------
// TF32 helpers
// ---------------------------------------------------------------------------
// cvt.rna.tf32.f32 requires a .b32 destination -> "=r" constraint.
__device__ __forceinline__ float to_tf32(float x) {
    uint32_t r;
    asm("cvt.rna.tf32.f32 %0, %1;" : "=r"(r) : "f"(x));
    return __uint_as_float(r);
}

#define MMA_TF32(D, Ar, Br)                                                  \
    asm volatile(                                                            \
        "mma.sync.aligned.m16n8k8.row.col.f32.tf32.tf32.f32 "                \
        "{%0,%1,%2,%3}, {%4,%5,%6,%7}, {%8,%9}, {%0,%1,%2,%3};"              \
        : "+f"((D)[0]), "+f"((D)[1]), "+f"((D)[2]), "+f"((D)[3])             \
        : "r"((Ar)[0]), "r"((Ar)[1]), "r"((Ar)[2]), "r"((Ar)[3]),            \
          "r"((Br)[0]), "r"((Br)[1]))

// ---------------------------------------------------------------------------
// TF32 tensor-core GEMM: C[M,N] = A[M,K] @ B[N,K]^T + bias, optional ReLU.
// REQUIRES: M%128==0, N%128==0, K%16==0. A row stride = lda. B stride = K.
// Block tile 128x128x16, 256 threads, 2x4 warp grid (warp tile 64x32),
// double-buffered smem, tf32 conversion at smem-store time.
// Smem layout [row][k] padded to 20 floats: fragment loads are conflict-free.
// ---------------------------------------------------------------------------
#define PADK 20

__global__ __launch_bounds__(256, 2) void sgemm_tf32_nt(
    const float* __restrict__ A, const float* __restrict__ B,
    float* __restrict__ C, const float* __restrict__ bias,
    int M, int N, int K, int lda, int doRelu)
{
    __shared__ float As[2][128][PADK];
    __shared__ float Bs[2][128][PADK];

    const int tid  = threadIdx.x;
    const int lane = tid & 31;
    const int warp = tid >> 5;
    const int wm   = warp >> 2;          // 0..1
    const int wn   = warp & 3;           // 0..3
    const int m0   = blockIdx.y * 128;
    const int n0   = blockIdx.x * 128;

    // global load mapping: row = tid/2 (0..127), k-base = (tid&1)*8
    const int grow = tid >> 1;
    const int gkb  = (tid & 1) * 8;
    const float* Aptr = A + (size_t)(m0 + grow) * lda + gkb;
    const float* Bptr = B + (size_t)(n0 + grow) * K + gkb;

    float acc[4][4][4];
#pragma unroll
    for (int a = 0; a < 4; a++)
#pragma unroll
        for (int b = 0; b < 4; b++)
#pragma unroll
            for (int c = 0; c < 4; c++) acc[a][b][c] = 0.f;

    const int nTiles = K >> 4;

    // prime buffer 0
    {
        float4 a0 = *(const float4*)(Aptr);
        float4 a1 = *(const float4*)(Aptr + 4);
        float4 b0 = *(const float4*)(Bptr);
        float4 b1 = *(const float4*)(Bptr + 4);
        As[0][grow][gkb+0] = to_tf32(a0.x); As[0][grow][gkb+1] = to_tf32(a0.y);
        As[0][grow][gkb+2] = to_tf32(a0.z); As[0][grow][gkb+3] = to_tf32(a0.w);
        As[0][grow][gkb+4] = to_tf32(a1.x); As[0][grow][gkb+5] = to_tf32(a1.y);
        As[0][grow][gkb+6] = to_tf32(a1.z); As[0][grow][gkb+7] = to_tf32(a1.w);
        Bs[0][grow][gkb+0] = to_tf32(b0.x); Bs[0][grow][gkb+1] = to_tf32(b0.y);
        Bs[0][grow][gkb+2] = to_tf32(b0.z); Bs[0][grow][gkb+3] = to_tf32(b0.w);
        Bs[0][grow][gkb+4] = to_tf32(b1.x); Bs[0][grow][gkb+5] = to_tf32(b1.y);
        Bs[0][grow][gkb+6] = to_tf32(b1.z); Bs[0][grow][gkb+7] = to_tf32(b1.w);
    }
    __syncthreads();

    int buf = 0;
    for (int t = 0; t < nTiles; t++) {
        const bool has = (t + 1) < nTiles;
        float4 na0, na1, nb0, nb1;
        if (has) {
            const int ko = (t + 1) << 4;
            na0 = *(const float4*)(Aptr + ko);
            na1 = *(const float4*)(Aptr + ko + 4);
            nb0 = *(const float4*)(Bptr + ko);
            nb1 = *(const float4*)(Bptr + ko + 4);
        }

        // compute on As/Bs[buf]
#pragma unroll
        for (int kk = 0; kk < 2; kk++) {
            const int kb = kk * 8;
            unsigned ar[4][4], br[4][2];
#pragma unroll
            for (int mi = 0; mi < 4; mi++) {
                const int r = wm*64 + mi*16 + (lane >> 2);
                ar[mi][0] = __float_as_uint(As[buf][r    ][kb     + (lane & 3)]);
                ar[mi][1] = __float_as_uint(As[buf][r + 8][kb     + (lane & 3)]);
                ar[mi][2] = __float_as_uint(As[buf][r    ][kb + 4 + (lane & 3)]);
                ar[mi][3] = __float_as_uint(As[buf][r + 8][kb + 4 + (lane & 3)]);
            }
#pragma unroll
            for (int ni = 0; ni < 4; ni++) {
                const int r = wn*32 + ni*8 + (lane >> 2);
                br[ni][0] = __float_as_uint(Bs[buf][r][kb     + (lane & 3)]);
                br[ni][1] = __float_as_uint(Bs[buf][r][kb + 4 + (lane & 3)]);
            }
#pragma unroll
            for (int mi = 0; mi < 4; mi++)
#pragma unroll
                for (int ni = 0; ni < 4; ni++)
                    MMA_TF32(acc[mi][ni], ar[mi], br[ni]);
        }

        if (has) {
            const int nb = buf ^ 1;
            As[nb][grow][gkb+0] = to_tf32(na0.x); As[nb][grow][gkb+1] = to_tf32(na0.y);
            As[nb][grow][gkb+2] = to_tf32(na0.z); As[nb][grow][gkb+3] = to_tf32(na0.w);
            As[nb][grow][gkb+4] = to_tf32(na1.x); As[nb][grow][gkb+5] = to_tf32(na1.y);
            As[nb][grow][gkb+6] = to_tf32(na1.z); As[nb][grow][gkb+7] = to_tf32(na1.w);
            Bs[nb][grow][gkb+0] = to_tf32(nb0.x); Bs[nb][grow][gkb+1] = to_tf32(nb0.y);
            Bs[nb][grow][gkb+2] = to_tf32(nb0.z); Bs[nb][grow][gkb+3] = to_tf32(nb0.w);
            Bs[nb][grow][gkb+4] = to_tf32(nb1.x); Bs[nb][grow][gkb+5] = to_tf32(nb1.y);
            Bs[nb][grow][gkb+6] = to_tf32(nb1.z); Bs[nb][grow][gkb+7] = to_tf32(nb1.w);
            __syncthreads();
            buf = nb;
        }
    }

    // epilogue
#pragma unroll
    for (int mi = 0; mi < 4; mi++) {
        const int row = m0 + wm*64 + mi*16 + (lane >> 2);
#pragma unroll
        for (int ni = 0; ni < 4; ni++) {
            const int col = n0 + wn*32 + ni*8 + 2*(lane & 3);
            const float bv0 = bias ? bias[col]     : 0.f;
            const float bv1 = bias ? bias[col + 1] : 0.f;
            float v0 = acc[mi][ni][0] + bv0;
            float v1 = acc[mi][ni][1] + bv1;
            float v2 = acc[mi][ni][2] + bv0;
            float v3 = acc[mi][ni][3] + bv1;
            if (doRelu) {
                v0 = fmaxf(v0, 0.f); v1 = fmaxf(v1, 0.f);
                v2 = fmaxf(v2, 0.f); v3 = fmaxf(v3, 0.f);
            }
            *(float2*)&C[(size_t)row * N + col]       = make_float2(v0, v1);
            *(float2*)&C[(size_t)(row + 8) * N + col] = make_float2(v2, v3);
        }
    }
}

// ---------------------------------------------------------------------------
// Fallback SIMT SGEMM (small / ragged shapes): C = A @ B^T + bias (ReLU opt.)
// ---------------------------------------------------------------------------
__global__ __launch_bounds__(256) void sgemm_nt(
    const float* __restrict__ A, const float* __restrict__ B,
    float* __restrict__ C, const float* __restrict__ bias,
    int M, int N, int K, int doRelu)
{
    __shared__ float As[8][128];
    __shared__ float Bs[8][128];

    const int tid = threadIdx.x;
    const int tx  = tid & 15;
    const int ty  = tid >> 4;
    const int m0  = blockIdx.y * 128;
    const int n0  = blockIdx.x * 128;
    const int lrow = tid >> 1;
    const int lk4  = (tid & 1) * 4;

    const bool aValid = (m0 + lrow) < M;
    const bool bValid = (n0 + lrow) < N;
    const float* Aptr = A + (size_t)(aValid ? (m0 + lrow) : 0) * K + lk4;
    const float* Bptr = B + (size_t)(bValid ? (n0 + lrow) : 0) * K + lk4;

    float acc[8][8];
#pragma unroll
    for (int i = 0; i < 8; i++)
#pragma unroll
        for (int j = 0; j < 8; j++) acc[i][j] = 0.f;

    for (int kt = 0; kt < K; kt += 8) {
        float4 a4 = aValid ? *(const float4*)(Aptr + kt) : make_float4(0.f,0.f,0.f,0.f);
        float4 b4 = bValid ? *(const float4*)(Bptr + kt) : make_float4(0.f,0.f,0.f,0.f);
        As[lk4+0][lrow] = a4.x; As[lk4+1][lrow] = a4.y;
        As[lk4+2][lrow] = a4.z; As[lk4+3][lrow] = a4.w;
        Bs[lk4+0][lrow] = b4.x; Bs[lk4+1][lrow] = b4.y;
        Bs[lk4+2][lrow] = b4.z; Bs[lk4+3][lrow] = b4.w;
        __syncthreads();
#pragma unroll
        for (int k = 0; k < 8; k++) {
            float a[8], b[8];
            *(float4*)&a[0] = *(const float4*)&As[k][ty*8];
            *(float4*)&a[4] = *(const float4*)&As[k][ty*8+4];
            *(float4*)&b[0] = *(const float4*)&Bs[k][tx*8];
            *(float4*)&b[4] = *(const float4*)&Bs[k][tx*8+4];
#pragma unroll
            for (int i = 0; i < 8; i++)
#pragma unroll
                for (int j = 0; j < 8; j++)
                    acc[i][j] += a[i]*b[j];
        }
        __syncthreads();
    }

#pragma unroll
    for (int i = 0; i < 8; i++) {
        int m = m0 + ty*8 + i;
        if (m < M) {
            float* Crow = C + (size_t)m * N + n0 + tx*8;
#pragma unroll
            for (int j = 0; j < 8; j++) {
                int n = n0 + tx*8 + j;
                if (n < N) {
                    float v = acc[i][j] + (bias ? bias[n] : 0.f);
                    if (doRelu) v = fmaxf(v, 0.f);
                    Crow[j] = v;
                }
            }
        }
    }
}

// ---------------------------------------------------------------------------
// Layer-0 attention from cached QKV0 [t][b][768]; last token's QKV = bias.
// One block per (b, head), 128 threads (4 warps), all queries.
// ---------------------------------------------------------------------------
__global__ __launch_bounds__(128) void attn0_kernel(
    const float* __restrict__ QKV0, const float* __restrict__ qkvb,
    float* __restrict__ out, int T)
{
    const int b = blockIdx.x >> 2, h = blockIdx.x & 3;
    const int tid = threadIdx.x, lane = tid & 31, w = tid >> 5;

    __shared__ float Kt[64*33];
    __shared__ float Vs[32*64];
    __shared__ float Qs[4][64];

    for (int idx = tid; idx < T*64; idx += 128) {
        const int s = idx >> 6, d = idx & 63;
        if (s == T-1) {
            Kt[d*33 + s] = qkvb[256 + h*64 + d];
            Vs[s*64 + d] = qkvb[512 + h*64 + d];
        } else {
            const float* p = QKV0 + ((size_t)s * B_ + b) * 768;
            Kt[d*33 + s] = p[256 + h*64 + d];
            Vs[s*64 + d] = p[512 + h*64 + d];
        }
    }
    __syncthreads();

    for (int t = w; t < T; t += 4) {
        const float* qsrc = (t == T-1) ? (qkvb + h*64)
                                       : (QKV0 + ((size_t)t * B_ + b) * 768 + h*64);
        float* Qrow = Qs[w];
        Qrow[lane]      = qsrc[lane];
        Qrow[lane + 32] = qsrc[lane + 32];
        __syncwarp();
        float sc;
        if (lane < T) {
            float s = 0.f;
#pragma unroll
            for (int d = 0; d < 64; d++) s += Qrow[d] * Kt[d*33 + lane];
            sc = s * 0.125f;
        } else sc = -3.4e38f;
        float m = sc;
#pragma unroll
        for (int o = 16; o > 0; o >>= 1) m = fmaxf(m, __shfl_xor_sync(0xffffffffu, m, o));
        float p = expf(sc - m);
        float sum = p;
#pragma unroll
        for (int o = 16; o > 0; o >>= 1) sum += __shfl_xor_sync(0xffffffffu, sum, o);
        float inv = 1.f / sum;
        float o0 = 0.f, o1 = 0.f;
        for (int s = 0; s < T; s++) {
            float ps = __shfl_sync(0xffffffffu, p, s);
            o0 += ps * Vs[s*64 + lane];
            o1 += ps * Vs[s*64 + 32 + lane];
        }
        float* op = out + ((size_t)b * T + t) * D_H_ + h*64;
        op[lane]      = o0 * inv;
        op[lane + 32] = o1 * inv;
        __syncwarp();
    }
}

// ---------------------------------------------------------------------------
// Layer-1 attention: K/V from KVB [b][t][512] (K at 0, V at 256),
// Q from Qlast [b][256]; last query only; out [b][256].
// ---------------------------------------------------------------------------
__global__ __launch_bounds__(128) void attn1_kernel(
    const float* __restrict__ KVB, const float* __restrict__ Qlast,
    float* __restrict__ out, int T)
{
    const int b = blockIdx.x >> 2, h = blockIdx.x & 3;
    const int tid = threadIdx.x, lane = tid & 31, w = tid >> 5;

    __shared__ float Kt[64*33];
    __shared__ float Vs[32*64];
    __shared__ float Qs[64];

    const float* base = KVB + (size_t)b * T * 512;
    for (int idx = tid; idx < T*64; idx += 128) {
        const int s = idx >> 6, d = idx & 63;
        Kt[d*33 + s] = base[(size_t)s*512 + h*64 + d];
        Vs[s*64 + d] = base[(size_t)s*512 + 256 + h*64 + d];
    }
    __syncthreads();

    if (w == 0) {
        const float* q = Qlast + (size_t)b * 256 + h*64;
        Qs[lane]      = q[lane];
        Qs[lane + 32] = q[lane + 32];
        __syncwarp();
        float sc;
        if (lane < T) {
            float s = 0.f;
#pragma unroll
            for (int d = 0; d < 64; d++) s += Qs[d] * Kt[d*33 + lane];
            sc = s * 0.125f;
        } else sc = -3.4e38f;
        float m = sc;
#pragma unroll
        for (int o = 16; o > 0; o >>= 1) m = fmaxf(m, __shfl_xor_sync(0xffffffffu, m, o));
        float p = expf(sc - m);
        float sum = p;
#pragma unroll
        for (int o = 16; o > 0; o >>= 1) sum += __shfl_xor_sync(0xffffffffu, sum, o);
        float inv = 1.f / sum;
        float o0 = 0.f, o1 = 0.f;
        for (int s = 0; s < T; s++) {
            float ps = __shfl_sync(0xffffffffu, p, s);
            o0 += ps * Vs[s*64 + lane];
            o1 += ps * Vs[s*64 + 32 + lane];
        }
        float* op = out + (size_t)b * D_H_ + h*64;
        op[lane]      = o0 * inv;
        op[lane + 32] = o1 * inv;
    }
}

// ---------------------------------------------------------------------------
// LayerNorm cores
// ---------------------------------------------------------------------------
__device__ __forceinline__ void ln_core(float v, float* dst, int d,
                                        const float* gamma, const float* beta)
{
    __shared__ float s1[8], s2[8];
    float sum = v, sq = v*v;
#pragma unroll
    for (int o = 16; o > 0; o >>= 1) {
        sum += __shfl_down_sync(0xffffffffu, sum, o);
        sq  += __shfl_down_sync(0xffffffffu, sq,  o);
    }
    const int wrp = d >> 5, lane = d & 31;
    if (lane == 0) { s1[wrp] = sum; s2[wrp] = sq; }
    __syncthreads();
    if (wrp == 0) {
        float a = (lane < 8) ? s1[lane] : 0.f;
        float c = (lane < 8) ? s2[lane] : 0.f;
#pragma unroll
        for (int o = 4; o > 0; o >>= 1) {
            a += __shfl_down_sync(0xffffffffu, a, o);
            c += __shfl_down_sync(0xffffffffu, c, o);
        }
        if (lane == 0) { s1[0] = a; s2[0] = c; }
    }
    __syncthreads();
    const float mean = s1[0] * (1.f/256.f);
    const float var  = s2[0] * (1.f/256.f) - mean*mean;
    const float r = rsqrtf(var + 1e-5f);
    dst[d] = (v - mean) * r * gamma[d] + beta[d];
}

// dst[row] = LN(resid[row*rStride + rOff] + delta[row]); rows of 256
__global__ __launch_bounds__(256) void add_ln(
    float* __restrict__ dst, const float* __restrict__ resid,
    const float* __restrict__ delta,
    const float* __restrict__ gamma, const float* __restrict__ beta,
    int rStride, int rOff)
{
    const int row = blockIdx.x, d = threadIdx.x;
    const float v = resid[((size_t)row * rStride + rOff) * D_H_ + d]
                  + delta[(size_t)row * D_H_ + d];
    ln_core(v, dst + (size_t)row * D_H_, d, gamma, beta);
}

// resid from MEMB [t][b][256] (zero for t == T-1); row = b*T + t
__global__ __launch_bounds__(256) void add_ln_mem(
    float* __restrict__ dst, const float* __restrict__ MEMB,
    const float* __restrict__ delta,
    const float* __restrict__ gamma, const float* __restrict__ beta, int T)
{
    const int row = blockIdx.x, d = threadIdx.x;
    const int t = row % T, b = row / T;
    float v = delta[(size_t)row * D_H_ + d];
    if (t < T-1) v += MEMB[((size_t)t * B_ + b) * D_H_ + d];
    ln_core(v, dst + (size_t)row * D_H_, d, gamma, beta);
}

// ---------------------------------------------------------------------------
// Glue kernels
// ---------------------------------------------------------------------------
__global__ void build_spkcat(float* __restrict__ SC, const float* __restrict__ POOLED,
                             const float* __restrict__ x, int j)
{
    int i = blockIdx.x * 256 + threadIdx.x;
    if (i >= 64 * 1536) return;
    int g = i / 1536, c = i % 1536;
    SC[i] = (c < 768) ? POOLED[(size_t)(g*8) * 768 + c]
                      : x[(size_t)((g*32 + j) * 8) * 768 + (c - 768)];
}

__global__ void build_xj(float* __restrict__ XJ, const float* __restrict__ POOLED,
                         const float* __restrict__ SPK, const float* __restrict__ x,
                         int j, int first)
{
    int i = blockIdx.x * 256 + threadIdx.x;
    if (i >= B_ * 768) return;
    int b = i / 768, c = i % 768;
    int g = b >> 3, p = b & 7;
    float v;
    if (first)       v = x[(size_t)((g*32 + j) * 8 + p) * 768 + c];
    else if (p == 0) v = SPK[(size_t)g * 768 + c];
    else             v = POOLED[(size_t)b * 768 + c];
    XJ[i] = v;
}

__global__ __launch_bounds__(256) void gat_finish(
    float* __restrict__ MEMj, const float* __restrict__ HG,
    const float* __restrict__ a_src, const float* __restrict__ a_dst,
    const float* __restrict__ gat_b)
{
    int g = blockIdx.x;
    int tid = threadIdx.x, lane = tid & 31, w = tid >> 5;
    __shared__ float sES[8][4], sED[8][4];
    const float* hgBase = HG + (size_t)g * 8 * 1024;

    {
        int p = w;
        const float* hp = hgBase + (size_t)p * 1024;
        for (int h = 0; h < 4; h++) {
            float s1 = 0.f, s2 = 0.f;
            const float* hr  = hp + h*256;
            const float* asr = a_src + h*256;
            const float* adr = a_dst + h*256;
            for (int d = lane; d < 256; d += 32) {
                float hv = hr[d];
                s1 += hv * asr[d];
                s2 += hv * adr[d];
            }
#pragma unroll
            for (int o = 16; o > 0; o >>= 1) {
                s1 += __shfl_down_sync(0xffffffffu, s1, o);
                s2 += __shfl_down_sync(0xffffffffu, s2, o);
            }
            if (lane == 0) { sES[p][h] = s1; sED[p][h] = s2; }
        }
    }
    __syncthreads();

    int o = tid;
    for (int d = 0; d < 8; d++) {
        float val = 0.f;
        if (d == 0) {
#pragma unroll
            for (int h = 0; h < 4; h++)
                val += hgBase[h*256 + o];
        } else {
#pragma unroll
            for (int h = 0; h < 4; h++) {
                float e0 = sES[0][h] + sED[d][h];
                float e1 = sES[d][h] + sED[d][h];
                e0 = (e0 > 0.f) ? e0 : 0.2f*e0;
                e1 = (e1 > 0.f) ? e1 : 0.2f*e1;
                float m  = fmaxf(e0, e1);
                float w0 = expf(e0 - m), w1 = expf(e1 - m);
                float inv = 1.f / (w0 + w1);
                val += (w0 * hgBase[h*256 + o] +
                        w1 * hgBase[(size_t)d*1024 + h*256 + o]) * inv;
            }
        }
        MEMj[(size_t)(g*8 + d) * D_H_ + o] = 0.25f * val + gat_b[o];
    }
}

__global__ __launch_bounds__(32) void cls_out(
    float* __restrict__ out, const float* __restrict__ MEMB,
    const float* __restrict__ w, const float* __restrict__ bias)
{
    int r = blockIdx.x;
    int lane = threadIdx.x;
    int g = r >> 5, s = r & 31;
    const float* v = MEMB + ((size_t)s * B_ + g*8) * D_H_;
    for (int c = 0; c < 7; c++) {
        float sum = 0.f;
        for (int d = lane; d < 256; d += 32) sum += v[d] * w[c*256 + d];
#pragma unroll
        for (int o = 16; o > 0; o >>= 1) sum += __shfl_down_sync(0xffffffffu, sum, o);
        if (lane == 0) out[(size_t)r*7 + c] = sum + bias[c];
    }
}

// ---------------------------------------------------------------------------
// Host orchestration
// ---------------------------------------------------------------------------
static inline void gemm_tc(float* C, const float* A, const float* Bw, const float* bias,
                           int M, int N, int K, int lda, int relu)
{
    dim3 grid(N / 128, M / 128);
    sgemm_tf32_nt<<<grid, 256>>>(A, Bw, C, bias, M, N, K, lda, relu);
}

extern "C" void kernel_launch(void* const* d_in, const int* in_sizes, int n_in,
                              void* d_out, int out_size)
{
    (void)in_sizes; (void)n_in; (void)out_size;

    const float* x      = (const float*)d_in[0];
    const float* gat_w  = (const float*)d_in[3];
    const float* a_src  = (const float*)d_in[4];
    const float* a_dst  = (const float*)d_in[5];
    const float* gat_b  = (const float*)d_in[6];
    const float* qkv_w  = (const float*)d_in[7];
    const float* qkv_b  = (const float*)d_in[8];
    const float* out_w  = (const float*)d_in[9];
    const float* out_b  = (const float*)d_in[10];
    const float* ln1_g  = (const float*)d_in[11];
    const float* ln1_b  = (const float*)d_in[12];
    const float* ff1_w  = (const float*)d_in[13];
    const float* ff1_b  = (const float*)d_in[14];
    const float* ff2_w  = (const float*)d_in[15];
    const float* ff2_b  = (const float*)d_in[16];
    const float* ln2_g  = (const float*)d_in[17];
    const float* ln2_b  = (const float*)d_in[18];
    const float* proj_w = (const float*)d_in[19];
    const float* proj_b = (const float*)d_in[20];
    const float* spk_w  = (const float*)d_in[21];
    const float* spk_b  = (const float*)d_in[22];
    const float* cls_w  = (const float*)d_in[23];
    const float* cls_b  = (const float*)d_in[24];

    float* pool = nullptr;
    cudaGetSymbolAddress((void**)&pool, g_pool);

    float* QKV0   = pool + OFF_QKV0;
    float* H      = pool + OFF_H;
    float* AO     = pool + OFF_AO;
    float* FFB    = pool + OFF_FFB;
    float* T256   = pool + OFF_T256;
    float* KVB    = pool + OFF_KVB;
    float* MEMB   = pool + OFF_MEM;
    float* Qlast  = pool + OFF_QL;
    float* XJ     = pool + OFF_XJ;
    float* POOLED = pool + OFF_POOLED;
    float* HG     = pool + OFF_HG;
    float* SC     = pool + OFF_SC;
    float* SPK    = pool + OFF_SPK;
    float* C_ATT  = pool + OFF_CATT;
    float* C_H    = pool + OFF_CH;
    float* C_T1   = pool + OFF_CT1;
    float* C_T2   = pool + OFF_CT2;

    const float* qkv_w1 = qkv_w + 768*256;
    const float* qkv_b1 = qkv_b + 768;

    for (int j = 0; j < S_; j++) {
        if (j > 0) {
            const int T  = j + 1;
            const int NT = B_ * T;

            // ---- layer 0 (QKV cached in QKV0; zero-token QKV == bias) ----
            attn0_kernel<<<B_*NH_T_, 128>>>(QKV0, qkv_b, AO, T);
            gemm_tc(T256, AO, out_w, out_b, NT, 256, 256, 256, 0);
            add_ln_mem<<<NT, 256>>>(H, MEMB, T256, ln1_g, ln1_b, T);
            gemm_tc(FFB, H, ff1_w, ff1_b, NT, 2048, 256, 256, 1);
            gemm_tc(T256, FFB, ff2_w, ff2_b, NT, 256, 2048, 2048, 0);
            add_ln<<<NT, 256>>>(H, H, T256, ln2_g, ln2_b, 1, 0);

            // ---- layer 1: K/V for all tokens, Q for last tokens only ----
            gemm_tc(KVB, H, qkv_w1 + 256*256, qkv_b1 + 256, NT, 512, 256, 256, 0);
            gemm_tc(Qlast, H + (size_t)(T-1)*256, qkv_w1, qkv_b1, 512, 256, 256, T*256, 0);
            attn1_kernel<<<B_*NH_T_, 128>>>(KVB, Qlast, C_ATT, T);
            gemm_tc(C_T1, C_ATT, out_w + 256*256, out_b + 256, 512, 256, 256, 256, 0);
            add_ln<<<B_, 256>>>(C_H, H, C_T1, ln1_g + 256, ln1_b + 256, T, T-1);
            gemm_tc(C_T1, C_H, ff1_w + 2048*256, ff1_b + 2048, 512, 2048, 256, 256, 1);
            gemm_tc(C_T2, C_T1, ff2_w + 256*2048, ff2_b + 256, 512, 256, 2048, 2048, 0);
            add_ln<<<B_, 256>>>(C_H, C_H, C_T2, ln2_g + 256, ln2_b + 256, 1, 0);

            // ---- pooled projection + speaker path ----
            gemm_tc(POOLED, C_H, proj_w, proj_b, 512, 768, 256, 256, 0);
            build_spkcat<<<(64*1536 + 255)/256, 256>>>(SC, POOLED, x, j);
            {
                dim3 grid((768 + 127)/128, 1);
                sgemm_nt<<<grid, 256>>>(SC, spk_w, SPK, spk_b, 64, 768, 1536, 1);
            }
            build_xj<<<(B_*768 + 255)/256, 256>>>(XJ, POOLED, SPK, x, j, 0);
        } else {
            build_xj<<<(B_*768 + 255)/256, 256>>>(XJ, POOLED, SPK, x, 0, 1);
        }

        // ---- GAT ----
        gemm_tc(HG, XJ, gat_w, nullptr, 512, 1024, 768, 768, 0);
        gat_finish<<<G_, 256>>>(MEMB + (size_t)j * B_ * D_H_, HG, a_src, a_dst, gat_b);

        // ---- cache layer-0 QKV of the new memory row (used by later steps) ----
        if (j < S_ - 1)
            gemm_tc(QKV0 + (size_t)j * B_ * 768, MEMB + (size_t)j * B_ * D_H_,
                    qkv_w, qkv_b, 512, 768, 256, 256, 0);
    }

    cls_out<<<G_*S_, 32>>>((float*)d_out, MEMB, cls_w, cls_b);
}

// round 7
// speedup vs baseline: 2.9988x; 1.3536x over previous
#include <cuda_runtime.h>
#include <cmath>
#include <cstddef>
#include <cstdint>

// ---------------------------------------------------------------------------
// Problem constants
// ---------------------------------------------------------------------------
#define G_      64
#define S_      32
#define P_      8
#define D_IN_   768
#define D_H_    256
#define HEADS_  4
#define D_FF_   2048
#define NH_T_   4
#define B_      512         // G*P sequences
#define MAXT_   32
#define MAXNT_  (B_*MAXT_)  // 16384 tokens max

// ---------------------------------------------------------------------------
// Scratch pool (static __device__; no allocation allowed)
// ---------------------------------------------------------------------------
#define OFF_QKV0   0u                                  // [32][512][768] cached L0 qkv
#define OFF_H      (OFF_QKV0 + 32u*512u*768u)          // [16384][256]
#define OFF_AO     (OFF_H    + 16384u*256u)            // [16384][256]
#define OFF_FFB    (OFF_AO   + 16384u*256u)            // [16384][2048]
#define OFF_T256   (OFF_FFB  + 16384u*2048u)           // [16384][256]
#define OFF_KVB    (OFF_T256 + 16384u*256u)            // [16384][512]
#define OFF_MEM    (OFF_KVB  + 16384u*512u)            // [32][512][256]
#define OFF_QL     (OFF_MEM  + 32u*512u*256u)          // [512][256]
#define OFF_XJ     (OFF_QL   + 512u*256u)              // [512][768]
#define OFF_POOLED (OFF_XJ   + 512u*768u)              // [512][768]
#define OFF_HG     (OFF_POOLED + 512u*768u)            // [512][1024]
#define OFF_SC     (OFF_HG   + 512u*1024u)             // [64][1536]
#define OFF_SPK    (OFF_SC   + 64u*1536u)              // [64][768]
#define OFF_CATT   (OFF_SPK  + 64u*768u)               // [512][256]
#define OFF_CH     (OFF_CATT + 512u*256u)              // [512][256]
#define OFF_CT1    (OFF_CH   + 512u*256u)              // [512][2048]
#define OFF_CT2    (OFF_CT1  + 512u*2048u)             // [512][256]
#define OFF_P4     (OFF_CT2  + 512u*256u)              // [4][16384][256] split-K partials
#define POOL_SZ    (OFF_P4   + 4u*16384u*256u)

__device__ float g_pool[POOL_SZ];

// ---------------------------------------------------------------------------
// TF32 helpers
// ---------------------------------------------------------------------------
__device__ __forceinline__ float to_tf32(float x) {
    uint32_t r;
    asm("cvt.rna.tf32.f32 %0, %1;" : "=r"(r) : "f"(x));
    return __uint_as_float(r);
}

#define MMA_TF32(D, Ar, Br)                                                  \
    asm volatile(                                                            \
        "mma.sync.aligned.m16n8k8.row.col.f32.tf32.tf32.f32 "                \
        "{%0,%1,%2,%3}, {%4,%5,%6,%7}, {%8,%9}, {%0,%1,%2,%3};"              \
        : "+f"((D)[0]), "+f"((D)[1]), "+f"((D)[2]), "+f"((D)[3])             \
        : "r"((Ar)[0]), "r"((Ar)[1]), "r"((Ar)[2]), "r"((Ar)[3]),            \
          "r"((Br)[0]), "r"((Br)[1]))

// ---------------------------------------------------------------------------
// TF32 tensor-core GEMM with fragment-packed shared memory.
//   C[z] = A[:, z*kLen : (z+1)*kLen] @ B[:, z*kLen:...]^T (+ bias, ReLU)
// Block tile 128x128x16, 256 threads, 2x4 warps (warp tile 64x32), double
// buffered. Producer scatters tf32 values directly into mma fragment order:
//   A slot: [mt(8)][kc(2)][lane(32)][reg(4)]  -> consumer LDS.128
//   B slot: [nt(16)][kc(2)][lane(32)][reg(2)] -> consumer LDS.64
// Requires N%128==0, kLen%16==0. M guarded (loads clamp, stores masked).
// ---------------------------------------------------------------------------
__global__ __launch_bounds__(256, 2) void sgemm_tf32_nt(
    const float* __restrict__ A, const float* __restrict__ B,
    float* __restrict__ C, const float* __restrict__ bias,
    int M, int N, int kLen, int lda, int ldb, int doRelu, int cStrideZ)
{
    __shared__ float As[2][2048];
    __shared__ float Bs[2][2048];

    const int tid  = threadIdx.x;
    const int lane = tid & 31;
    const int warp = tid >> 5;
    const int wm   = warp >> 2;          // 0..1
    const int wn   = warp & 3;           // 0..3
    const int m0   = blockIdx.y * 128;
    const int n0   = blockIdx.x * 128;
    const int z    = blockIdx.z;

    // global load mapping: row = tid/2 (0..127), k-base = (tid&1)*8
    const int grow = tid >> 1;
    const int gkb  = (tid & 1) * 8;

    int arow = m0 + grow; if (arow >= M) arow = M - 1;
    const float* Aptr = A + (size_t)arow * lda + (size_t)z * kLen + gkb;
    const float* Bptr = B + (size_t)(n0 + grow) * ldb + (size_t)z * kLen + gkb;

    // fragment-slot offsets for this producer thread
    const int mt  = grow >> 4, r16 = grow & 15;
    const int nt  = grow >> 3, n8  = grow & 7;
    const int kc  = gkb >> 3;
    int aSlot[8], bSlot[8];
#pragma unroll
    for (int i = 0; i < 8; i++) {
        aSlot[i] = ((mt*2 + kc)*32 + ((r16 & 7) << 2) + (i & 3))*4
                 + (r16 >> 3) + ((i >> 2) << 1);
        bSlot[i] = ((nt*2 + kc)*32 + (n8 << 2) + (i & 3))*2 + (i >> 2);
    }

    float acc[4][4][4];
#pragma unroll
    for (int a = 0; a < 4; a++)
#pragma unroll
        for (int b = 0; b < 4; b++)
#pragma unroll
            for (int c = 0; c < 4; c++) acc[a][b][c] = 0.f;

    const int nTiles = kLen >> 4;

    // prime buffer 0
    {
        float4 a0 = *(const float4*)(Aptr);
        float4 a1 = *(const float4*)(Aptr + 4);
        float4 b0 = *(const float4*)(Bptr);
        float4 b1 = *(const float4*)(Bptr + 4);
        float av[8] = {a0.x,a0.y,a0.z,a0.w,a1.x,a1.y,a1.z,a1.w};
        float bv[8] = {b0.x,b0.y,b0.z,b0.w,b1.x,b1.y,b1.z,b1.w};
#pragma unroll
        for (int i = 0; i < 8; i++) {
            As[0][aSlot[i]] = to_tf32(av[i]);
            Bs[0][bSlot[i]] = to_tf32(bv[i]);
        }
    }
    __syncthreads();

    int buf = 0;
    for (int t = 0; t < nTiles; t++) {
        const bool has = (t + 1) < nTiles;
        float4 na0, na1, nb0, nb1;
        if (has) {
            const int ko = (t + 1) << 4;
            na0 = *(const float4*)(Aptr + ko);
            na1 = *(const float4*)(Aptr + ko + 4);
            nb0 = *(const float4*)(Bptr + ko);
            nb1 = *(const float4*)(Bptr + ko + 4);
        }

        // compute on fragment-packed As/Bs[buf]
#pragma unroll
        for (int kk = 0; kk < 2; kk++) {
            unsigned ar[4][4], br[4][2];
#pragma unroll
            for (int mi = 0; mi < 4; mi++) {
                const float4 af = *(const float4*)
                    &As[buf][(((wm*4 + mi)*2 + kk)*32 + lane)*4];
                ar[mi][0] = __float_as_uint(af.x);
                ar[mi][1] = __float_as_uint(af.y);
                ar[mi][2] = __float_as_uint(af.z);
                ar[mi][3] = __float_as_uint(af.w);
            }
#pragma unroll
            for (int ni = 0; ni < 4; ni++) {
                const float2 bf = *(const float2*)
                    &Bs[buf][(((wn*4 + ni)*2 + kk)*32 + lane)*2];
                br[ni][0] = __float_as_uint(bf.x);
                br[ni][1] = __float_as_uint(bf.y);
            }
#pragma unroll
            for (int mi = 0; mi < 4; mi++)
#pragma unroll
                for (int ni = 0; ni < 4; ni++)
                    MMA_TF32(acc[mi][ni], ar[mi], br[ni]);
        }

        if (has) {
            const int nb = buf ^ 1;
            float av[8] = {na0.x,na0.y,na0.z,na0.w,na1.x,na1.y,na1.z,na1.w};
            float bv[8] = {nb0.x,nb0.y,nb0.z,nb0.w,nb1.x,nb1.y,nb1.z,nb1.w};
#pragma unroll
            for (int i = 0; i < 8; i++) {
                As[nb][aSlot[i]] = to_tf32(av[i]);
                Bs[nb][bSlot[i]] = to_tf32(bv[i]);
            }
            __syncthreads();
            buf = nb;
        }
    }

    // epilogue
    float* Cz = C + (size_t)z * cStrideZ;
#pragma unroll
    for (int mi = 0; mi < 4; mi++) {
        const int row = m0 + wm*64 + mi*16 + (lane >> 2);
#pragma unroll
        for (int ni = 0; ni < 4; ni++) {
            const int col = n0 + wn*32 + ni*8 + 2*(lane & 3);
            const float bv0 = bias ? bias[col]     : 0.f;
            const float bv1 = bias ? bias[col + 1] : 0.f;
            float v0 = acc[mi][ni][0] + bv0;
            float v1 = acc[mi][ni][1] + bv1;
            float v2 = acc[mi][ni][2] + bv0;
            float v3 = acc[mi][ni][3] + bv1;
            if (doRelu) {
                v0 = fmaxf(v0, 0.f); v1 = fmaxf(v1, 0.f);
                v2 = fmaxf(v2, 0.f); v3 = fmaxf(v3, 0.f);
            }
            if (row < M)
                *(float2*)&Cz[(size_t)row * N + col]       = make_float2(v0, v1);
            if (row + 8 < M)
                *(float2*)&Cz[(size_t)(row + 8) * N + col] = make_float2(v2, v3);
        }
    }
}

// ---------------------------------------------------------------------------
// Layer-0 attention from cached QKV0 [t][b][768]; last token's QKV = bias.
// ---------------------------------------------------------------------------
__global__ __launch_bounds__(128) void attn0_kernel(
    const float* __restrict__ QKV0, const float* __restrict__ qkvb,
    float* __restrict__ out, int T)
{
    const int b = blockIdx.x >> 2, h = blockIdx.x & 3;
    const int tid = threadIdx.x, lane = tid & 31, w = tid >> 5;

    __shared__ float Kt[64*33];
    __shared__ float Vs[32*64];
    __shared__ float Qs[4][64];

    for (int idx = tid; idx < T*64; idx += 128) {
        const int s = idx >> 6, d = idx & 63;
        if (s == T-1) {
            Kt[d*33 + s] = qkvb[256 + h*64 + d];
            Vs[s*64 + d] = qkvb[512 + h*64 + d];
        } else {
            const float* p = QKV0 + ((size_t)s * B_ + b) * 768;
            Kt[d*33 + s] = p[256 + h*64 + d];
            Vs[s*64 + d] = p[512 + h*64 + d];
        }
    }
    __syncthreads();

    for (int t = w; t < T; t += 4) {
        const float* qsrc = (t == T-1) ? (qkvb + h*64)
                                       : (QKV0 + ((size_t)t * B_ + b) * 768 + h*64);
        float* Qrow = Qs[w];
        Qrow[lane]      = qsrc[lane];
        Qrow[lane + 32] = qsrc[lane + 32];
        __syncwarp();
        float sc;
        if (lane < T) {
            float s = 0.f;
#pragma unroll
            for (int d = 0; d < 64; d++) s += Qrow[d] * Kt[d*33 + lane];
            sc = s * 0.125f;
        } else sc = -3.4e38f;
        float m = sc;
#pragma unroll
        for (int o = 16; o > 0; o >>= 1) m = fmaxf(m, __shfl_xor_sync(0xffffffffu, m, o));
        float p = expf(sc - m);
        float sum = p;
#pragma unroll
        for (int o = 16; o > 0; o >>= 1) sum += __shfl_xor_sync(0xffffffffu, sum, o);
        float inv = 1.f / sum;
        float o0 = 0.f, o1 = 0.f;
        for (int s = 0; s < T; s++) {
            float ps = __shfl_sync(0xffffffffu, p, s);
            o0 += ps * Vs[s*64 + lane];
            o1 += ps * Vs[s*64 + 32 + lane];
        }
        float* op = out + ((size_t)b * T + t) * D_H_ + h*64;
        op[lane]      = o0 * inv;
        op[lane + 32] = o1 * inv;
        __syncwarp();
    }
}

// ---------------------------------------------------------------------------
// Layer-1 attention: K/V from KVB [b][t][512], Q from Qlast [b][256].
// ---------------------------------------------------------------------------
__global__ __launch_bounds__(128) void attn1_kernel(
    const float* __restrict__ KVB, const float* __restrict__ Qlast,
    float* __restrict__ out, int T)
{
    const int b = blockIdx.x >> 2, h = blockIdx.x & 3;
    const int tid = threadIdx.x, lane = tid & 31, w = tid >> 5;

    __shared__ float Kt[64*33];
    __shared__ float Vs[32*64];
    __shared__ float Qs[64];

    const float* base = KVB + (size_t)b * T * 512;
    for (int idx = tid; idx < T*64; idx += 128) {
        const int s = idx >> 6, d = idx & 63;
        Kt[d*33 + s] = base[(size_t)s*512 + h*64 + d];
        Vs[s*64 + d] = base[(size_t)s*512 + 256 + h*64 + d];
    }
    __syncthreads();

    if (w == 0) {
        const float* q = Qlast + (size_t)b * 256 + h*64;
        Qs[lane]      = q[lane];
        Qs[lane + 32] = q[lane + 32];
        __syncwarp();
        float sc;
        if (lane < T) {
            float s = 0.f;
#pragma unroll
            for (int d = 0; d < 64; d++) s += Qs[d] * Kt[d*33 + lane];
            sc = s * 0.125f;
        } else sc = -3.4e38f;
        float m = sc;
#pragma unroll
        for (int o = 16; o > 0; o >>= 1) m = fmaxf(m, __shfl_xor_sync(0xffffffffu, m, o));
        float p = expf(sc - m);
        float sum = p;
#pragma unroll
        for (int o = 16; o > 0; o >>= 1) sum += __shfl_xor_sync(0xffffffffu, sum, o);
        float inv = 1.f / sum;
        float o0 = 0.f, o1 = 0.f;
        for (int s = 0; s < T; s++) {
            float ps = __shfl_sync(0xffffffffu, p, s);
            o0 += ps * Vs[s*64 + lane];
            o1 += ps * Vs[s*64 + 32 + lane];
        }
        float* op = out + (size_t)b * D_H_ + h*64;
        op[lane]      = o0 * inv;
        op[lane + 32] = o1 * inv;
    }
}

// ---------------------------------------------------------------------------
// LayerNorm cores
// ---------------------------------------------------------------------------
__device__ __forceinline__ void ln_core(float v, float* dst, int d,
                                        const float* gamma, const float* beta)
{
    __shared__ float s1[8], s2[8];
    float sum = v, sq = v*v;
#pragma unroll
    for (int o = 16; o > 0; o >>= 1) {
        sum += __shfl_down_sync(0xffffffffu, sum, o);
        sq  += __shfl_down_sync(0xffffffffu, sq,  o);
    }
    const int wrp = d >> 5, lane = d & 31;
    if (lane == 0) { s1[wrp] = sum; s2[wrp] = sq; }
    __syncthreads();
    if (wrp == 0) {
        float a = (lane < 8) ? s1[lane] : 0.f;
        float c = (lane < 8) ? s2[lane] : 0.f;
#pragma unroll
        for (int o = 4; o > 0; o >>= 1) {
            a += __shfl_down_sync(0xffffffffu, a, o);
            c += __shfl_down_sync(0xffffffffu, c, o);
        }
        if (lane == 0) { s1[0] = a; s2[0] = c; }
    }
    __syncthreads();
    const float mean = s1[0] * (1.f/256.f);
    const float var  = s2[0] * (1.f/256.f) - mean*mean;
    const float r = rsqrtf(var + 1e-5f);
    dst[d] = (v - mean) * r * gamma[d] + beta[d];
}

// dst[row] = LN(resid[row*rStride + rOff] + delta[row])
__global__ __launch_bounds__(256) void add_ln(
    float* __restrict__ dst, const float* __restrict__ resid,
    const float* __restrict__ delta,
    const float* __restrict__ gamma, const float* __restrict__ beta,
    int rStride, int rOff)
{
    const int row = blockIdx.x, d = threadIdx.x;
    const float v = resid[((size_t)row * rStride + rOff) * D_H_ + d]
                  + delta[(size_t)row * D_H_ + d];
    ln_core(v, dst + (size_t)row * D_H_, d, gamma, beta);
}

// dst[row] = LN(resid[row] + Σ_{z<4} parts[z*pStride + row*256+d] + dbias[d])
__global__ __launch_bounds__(256) void add_ln_p4(
    float* __restrict__ dst, const float* __restrict__ resid,
    const float* __restrict__ parts, int pStride,
    const float* __restrict__ dbias,
    const float* __restrict__ gamma, const float* __restrict__ beta)
{
    const int row = blockIdx.x, d = threadIdx.x;
    const size_t i = (size_t)row * D_H_ + d;
    float v = resid[i] + dbias[d]
            + parts[i] + parts[(size_t)pStride + i]
            + parts[2*(size_t)pStride + i] + parts[3*(size_t)pStride + i];
    ln_core(v, dst + (size_t)row * D_H_, d, gamma, beta);
}

// resid from MEMB [t][b][256] (zero for t == T-1); row = b*T + t
__global__ __launch_bounds__(256) void add_ln_mem(
    float* __restrict__ dst, const float* __restrict__ MEMB,
    const float* __restrict__ delta,
    const float* __restrict__ gamma, const float* __restrict__ beta, int T)
{
    const int row = blockIdx.x, d = threadIdx.x;
    const int t = row % T, b = row / T;
    float v = delta[(size_t)row * D_H_ + d];
    if (t < T-1) v += MEMB[((size_t)t * B_ + b) * D_H_ + d];
    ln_core(v, dst + (size_t)row * D_H_, d, gamma, beta);
}

// ---------------------------------------------------------------------------
// Split-K reduce (+bias, ReLU) for the spk GEMM
// ---------------------------------------------------------------------------
__global__ void reduce4_relu(float* __restrict__ dst, const float* __restrict__ parts,
                             int pStride, const float* __restrict__ bias,
                             int rows, int cols)
{
    int i = blockIdx.x * 256 + threadIdx.x;
    if (i >= rows * cols) return;
    int c = i % cols;
    float v = bias[c] + parts[i] + parts[(size_t)pStride + i]
            + parts[2*(size_t)pStride + i] + parts[3*(size_t)pStride + i];
    dst[i] = fmaxf(v, 0.f);
}

// ---------------------------------------------------------------------------
// Glue kernels
// ---------------------------------------------------------------------------
__global__ void build_spkcat(float* __restrict__ SC, const float* __restrict__ POOLED,
                             const float* __restrict__ x, int j)
{
    int i = blockIdx.x * 256 + threadIdx.x;
    if (i >= 64 * 1536) return;
    int g = i / 1536, c = i % 1536;
    SC[i] = (c < 768) ? POOLED[(size_t)(g*8) * 768 + c]
                      : x[(size_t)((g*32 + j) * 8) * 768 + (c - 768)];
}

__global__ void build_xj(float* __restrict__ XJ, const float* __restrict__ POOLED,
                         const float* __restrict__ SPK, const float* __restrict__ x,
                         int j, int first)
{
    int i = blockIdx.x * 256 + threadIdx.x;
    if (i >= B_ * 768) return;
    int b = i / 768, c = i % 768;
    int g = b >> 3, p = b & 7;
    float v;
    if (first)       v = x[(size_t)((g*32 + j) * 8 + p) * 768 + c];
    else if (p == 0) v = SPK[(size_t)g * 768 + c];
    else             v = POOLED[(size_t)b * 768 + c];
    XJ[i] = v;
}

__global__ __launch_bounds__(256) void gat_finish(
    float* __restrict__ MEMj, const float* __restrict__ HG,
    const float* __restrict__ a_src, const float* __restrict__ a_dst,
    const float* __restrict__ gat_b)
{
    int g = blockIdx.x;
    int tid = threadIdx.x, lane = tid & 31, w = tid >> 5;
    __shared__ float sES[8][4], sED[8][4];
    const float* hgBase = HG + (size_t)g * 8 * 1024;

    {
        int p = w;
        const float* hp = hgBase + (size_t)p * 1024;
        for (int h = 0; h < 4; h++) {
            float s1 = 0.f, s2 = 0.f;
            const float* hr  = hp + h*256;
            const float* asr = a_src + h*256;
            const float* adr = a_dst + h*256;
            for (int d = lane; d < 256; d += 32) {
                float hv = hr[d];
                s1 += hv * asr[d];
                s2 += hv * adr[d];
            }
#pragma unroll
            for (int o = 16; o > 0; o >>= 1) {
                s1 += __shfl_down_sync(0xffffffffu, s1, o);
                s2 += __shfl_down_sync(0xffffffffu, s2, o);
            }
            if (lane == 0) { sES[p][h] = s1; sED[p][h] = s2; }
        }
    }
    __syncthreads();

    int o = tid;
    for (int d = 0; d < 8; d++) {
        float val = 0.f;
        if (d == 0) {
#pragma unroll
            for (int h = 0; h < 4; h++)
                val += hgBase[h*256 + o];
        } else {
#pragma unroll
            for (int h = 0; h < 4; h++) {
                float e0 = sES[0][h] + sED[d][h];
                float e1 = sES[d][h] + sED[d][h];
                e0 = (e0 > 0.f) ? e0 : 0.2f*e0;
                e1 = (e1 > 0.f) ? e1 : 0.2f*e1;
                float m  = fmaxf(e0, e1);
                float w0 = expf(e0 - m), w1 = expf(e1 - m);
                float inv = 1.f / (w0 + w1);
                val += (w0 * hgBase[h*256 + o] +
                        w1 * hgBase[(size_t)d*1024 + h*256 + o]) * inv;
            }
        }
        MEMj[(size_t)(g*8 + d) * D_H_ + o] = 0.25f * val + gat_b[o];
    }
}

__global__ __launch_bounds__(32) void cls_out(
    float* __restrict__ out, const float* __restrict__ MEMB,
    const float* __restrict__ w, const float* __restrict__ bias)
{
    int r = blockIdx.x;
    int lane = threadIdx.x;
    int g = r >> 5, s = r & 31;
    const float* v = MEMB + ((size_t)s * B_ + g*8) * D_H_;
    for (int c = 0; c < 7; c++) {
        float sum = 0.f;
        for (int d = lane; d < 256; d += 32) sum += v[d] * w[c*256 + d];
#pragma unroll
        for (int o = 16; o > 0; o >>= 1) sum += __shfl_down_sync(0xffffffffu, sum, o);
        if (lane == 0) out[(size_t)r*7 + c] = sum + bias[c];
    }
}

// ---------------------------------------------------------------------------
// Host orchestration
// ---------------------------------------------------------------------------
static inline void gemm_tc(float* C, const float* A, const float* Bw, const float* bias,
                           int M, int N, int K, int lda, int relu)
{
    dim3 grid(N / 128, (M + 127) / 128, 1);
    sgemm_tf32_nt<<<grid, 256>>>(A, Bw, C, bias, M, N, K, lda, K, relu, 0);
}

// split-K x4: partials to Cpart[z], bias deferred to the reducing consumer
static inline void gemm_tc_sk4(float* Cpart, const float* A, const float* Bw,
                               int M, int N, int K, int lda, int pStride)
{
    dim3 grid(N / 128, (M + 127) / 128, 4);
    sgemm_tf32_nt<<<grid, 256>>>(A, Bw, Cpart, nullptr, M, N, K/4, lda, K, 0, pStride);
}

extern "C" void kernel_launch(void* const* d_in, const int* in_sizes, int n_in,
                              void* d_out, int out_size)
{
    (void)in_sizes; (void)n_in; (void)out_size;

    const float* x      = (const float*)d_in[0];
    const float* gat_w  = (const float*)d_in[3];
    const float* a_src  = (const float*)d_in[4];
    const float* a_dst  = (const float*)d_in[5];
    const float* gat_b  = (const float*)d_in[6];
    const float* qkv_w  = (const float*)d_in[7];
    const float* qkv_b  = (const float*)d_in[8];
    const float* out_w  = (const float*)d_in[9];
    const float* out_b  = (const float*)d_in[10];
    const float* ln1_g  = (const float*)d_in[11];
    const float* ln1_b  = (const float*)d_in[12];
    const float* ff1_w  = (const float*)d_in[13];
    const float* ff1_b  = (const float*)d_in[14];
    const float* ff2_w  = (const float*)d_in[15];
    const float* ff2_b  = (const float*)d_in[16];
    const float* ln2_g  = (const float*)d_in[17];
    const float* ln2_b  = (const float*)d_in[18];
    const float* proj_w = (const float*)d_in[19];
    const float* proj_b = (const float*)d_in[20];
    const float* spk_w  = (const float*)d_in[21];
    const float* spk_b  = (const float*)d_in[22];
    const float* cls_w  = (const float*)d_in[23];
    const float* cls_b  = (const float*)d_in[24];

    float* pool = nullptr;
    cudaGetSymbolAddress((void**)&pool, g_pool);

    float* QKV0   = pool + OFF_QKV0;
    float* H      = pool + OFF_H;
    float* AO     = pool + OFF_AO;
    float* FFB    = pool + OFF_FFB;
    float* T256   = pool + OFF_T256;
    float* KVB    = pool + OFF_KVB;
    float* MEMB   = pool + OFF_MEM;
    float* Qlast  = pool + OFF_QL;
    float* XJ     = pool + OFF_XJ;
    float* POOLED = pool + OFF_POOLED;
    float* HG     = pool + OFF_HG;
    float* SC     = pool + OFF_SC;
    float* SPK    = pool + OFF_SPK;
    float* C_ATT  = pool + OFF_CATT;
    float* C_H    = pool + OFF_CH;
    float* C_T1   = pool + OFF_CT1;
    float* P4     = pool + OFF_P4;

    const float* qkv_w1 = qkv_w + 768*256;
    const float* qkv_b1 = qkv_b + 768;

    for (int j = 0; j < S_; j++) {
        if (j > 0) {
            const int T  = j + 1;
            const int NT = B_ * T;

            // ---- layer 0 (QKV cached in QKV0; zero-token QKV == bias) ----
            attn0_kernel<<<B_*NH_T_, 128>>>(QKV0, qkv_b, AO, T);
            gemm_tc(T256, AO, out_w, out_b, NT, 256, 256, 256, 0);
            add_ln_mem<<<NT, 256>>>(H, MEMB, T256, ln1_g, ln1_b, T);
            gemm_tc(FFB, H, ff1_w, ff1_b, NT, 2048, 256, 256, 1);
            gemm_tc_sk4(P4, FFB, ff2_w, NT, 256, 2048, 2048, NT*256);
            add_ln_p4<<<NT, 256>>>(H, H, P4, NT*256, ff2_b, ln2_g, ln2_b);

            // ---- layer 1: K/V for all tokens, Q for last tokens only ----
            gemm_tc(KVB, H, qkv_w1 + 256*256, qkv_b1 + 256, NT, 512, 256, 256, 0);
            gemm_tc(Qlast, H + (size_t)(T-1)*256, qkv_w1, qkv_b1, 512, 256, 256, T*256, 0);
            attn1_kernel<<<B_*NH_T_, 128>>>(KVB, Qlast, C_ATT, T);
            gemm_tc(T256, C_ATT, out_w + 256*256, out_b + 256, 512, 256, 256, 256, 0);
            add_ln<<<B_, 256>>>(C_H, H, T256, ln1_g + 256, ln1_b + 256, T, T-1);
            gemm_tc(C_T1, C_H, ff1_w + 2048*256, ff1_b + 2048, 512, 2048, 256, 256, 1);
            gemm_tc_sk4(P4, C_T1, ff2_w + 256*2048, 512, 256, 2048, 2048, 512*256);
            add_ln_p4<<<B_, 256>>>(C_H, C_H, P4, 512*256, ff2_b + 256,
                                   ln2_g + 256, ln2_b + 256);

            // ---- pooled projection + speaker path ----
            gemm_tc(POOLED, C_H, proj_w, proj_b, 512, 768, 256, 256, 0);
            build_spkcat<<<(64*1536 + 255)/256, 256>>>(SC, POOLED, x, j);
            gemm_tc_sk4(P4, SC, spk_w, 64, 768, 1536, 1536, 64*768);
            reduce4_relu<<<(64*768 + 255)/256, 256>>>(SPK, P4, 64*768, spk_b, 64, 768);
            build_xj<<<(B_*768 + 255)/256, 256>>>(XJ, POOLED, SPK, x, j, 0);
        } else {
            build_xj<<<(B_*768 + 255)/256, 256>>>(XJ, POOLED, SPK, x, 0, 1);
        }

        // ---- GAT ----
        gemm_tc(HG, XJ, gat_w, nullptr, 512, 1024, 768, 768, 0);
        gat_finish<<<G_, 256>>>(MEMB + (size_t)j * B_ * D_H_, HG, a_src, a_dst, gat_b);

        // ---- cache layer-0 QKV of the new memory row (used by later steps) ----
        if (j < S_ - 1)
            gemm_tc(QKV0 + (size_t)j * B_ * 768, MEMB + (size_t)j * B_ * D_H_,
                    qkv_w, qkv_b, 512, 768, 256, 256, 0);
    }

    cls_out<<<G_*S_, 32>>>((float*)d_out, MEMB, cls_w, cls_b);
}

// round 8
// speedup vs baseline: 3.5038x; 1.1684x over previous
#include <cuda_runtime.h>
#include <cmath>
#include <cstddef>
#include <cstdint>

// ---------------------------------------------------------------------------
// Problem constants
// ---------------------------------------------------------------------------
#define G_      64
#define S_      32
#define P_      8
#define D_IN_   768
#define D_H_    256
#define HEADS_  4
#define D_FF_   2048
#define NH_T_   4
#define B_      512         // G*P sequences
#define MAXT_   32
#define MAXNT_  (B_*MAXT_)  // 16384 tokens max

// ---------------------------------------------------------------------------
// Scratch pool (static __device__; no allocation allowed)
// ---------------------------------------------------------------------------
#define OFF_QKV0   0u                                  // [32][512][768] cached L0 qkv
#define OFF_H      (OFF_QKV0 + 32u*512u*768u)          // [16384][256]
#define OFF_AO     (OFF_H    + 16384u*256u)            // [16384][256]
#define OFF_FFB    (OFF_AO   + 16384u*256u)            // [16384][2048]
#define OFF_T256   (OFF_FFB  + 16384u*2048u)           // [16384][256]
#define OFF_KVB    (OFF_T256 + 16384u*256u)            // [16384][512]
#define OFF_MEM    (OFF_KVB  + 16384u*512u)            // [32][512][256]
#define OFF_QL     (OFF_MEM  + 32u*512u*256u)          // [512][256]
#define OFF_XJ     (OFF_QL   + 512u*256u)              // [512][768]
#define OFF_POOLED (OFF_XJ   + 512u*768u)              // [512][768]
#define OFF_HG     (OFF_POOLED + 512u*768u)            // [512][1024]
#define OFF_SC     (OFF_HG   + 512u*1024u)             // [64][1536]
#define OFF_SPK    (OFF_SC   + 64u*1536u)              // [64][768]
#define OFF_CATT   (OFF_SPK  + 64u*768u)               // [512][256]
#define OFF_CH     (OFF_CATT + 512u*256u)              // [512][256]
#define OFF_CT1    (OFF_CH   + 512u*256u)              // [512][2048]
#define OFF_CT2    (OFF_CT1  + 512u*2048u)             // [512][256]
#define OFF_P4     (OFF_CT2  + 512u*256u)              // [4][16384][256] split-K partials
#define POOL_SZ    (OFF_P4   + 4u*16384u*256u)

__device__ float g_pool[POOL_SZ];

// ---------------------------------------------------------------------------
// TF32 helpers
// ---------------------------------------------------------------------------
__device__ __forceinline__ float to_tf32(float x) {
    uint32_t r;
    asm("cvt.rna.tf32.f32 %0, %1;" : "=r"(r) : "f"(x));
    return __uint_as_float(r);
}

#define MMA_TF32(D, Ar, Br)                                                  \
    asm volatile(                                                            \
        "mma.sync.aligned.m16n8k8.row.col.f32.tf32.tf32.f32 "                \
        "{%0,%1,%2,%3}, {%4,%5,%6,%7}, {%8,%9}, {%0,%1,%2,%3};"              \
        : "+f"((D)[0]), "+f"((D)[1]), "+f"((D)[2]), "+f"((D)[3])             \
        : "r"((Ar)[0]), "r"((Ar)[1]), "r"((Ar)[2]), "r"((Ar)[3]),            \
          "r"((Br)[0]), "r"((Br)[1]))

// ---------------------------------------------------------------------------
// TF32 tensor-core GEMM with fragment-packed shared memory.
//   C[z] = A[:, z*kLen : (z+1)*kLen] @ B[:, z*kLen:...]^T (+ bias, ReLU)
// Block tile 128x128x16, 256 threads, 2x4 warps (warp tile 64x32), double
// buffered. Producer scatters tf32 values directly into mma fragment order
// (store order rotated per-thread to avoid STS bank conflicts):
//   A slot: [mt(8)][kc(2)][lane(32)][reg(4)]  -> consumer LDS.128
//   B slot: [nt(16)][kc(2)][lane(32)][reg(2)] -> consumer LDS.64
// Requires N%128==0, kLen%16==0. M guarded (loads clamp, stores masked).
// ---------------------------------------------------------------------------
__global__ __launch_bounds__(256, 2) void sgemm_tf32_nt(
    const float* __restrict__ A, const float* __restrict__ B,
    float* __restrict__ C, const float* __restrict__ bias,
    int M, int N, int kLen, int lda, int ldb, int doRelu, int cStrideZ)
{
    __shared__ float As[2][2048];
    __shared__ float Bs[2][2048];

    const int tid  = threadIdx.x;
    const int lane = tid & 31;
    const int warp = tid >> 5;
    const int wm   = warp >> 2;          // 0..1
    const int wn   = warp & 3;           // 0..3
    const int m0   = blockIdx.y * 128;
    const int n0   = blockIdx.x * 128;
    const int z    = blockIdx.z;

    // global load mapping: row = tid/2 (0..127), k-base = (tid&1)*8
    const int grow = tid >> 1;
    const int gkb  = (tid & 1) * 8;

    int arow = m0 + grow; if (arow >= M) arow = M - 1;
    const float* Aptr = A + (size_t)arow * lda + (size_t)z * kLen + gkb;
    const float* Bptr = B + (size_t)(n0 + grow) * ldb + (size_t)z * kLen + gkb;

    // fragment-slot offsets for this producer thread
    const int mt  = grow >> 4, r16 = grow & 15;
    const int nt  = grow >> 3, n8  = grow & 7;
    const int kc  = gkb >> 3;
    const int rot = grow & 7;            // per-thread store-order rotation
    int aSlot[8], bSlot[8];
#pragma unroll
    for (int i = 0; i < 8; i++) {
        aSlot[i] = ((mt*2 + kc)*32 + ((r16 & 7) << 2) + (i & 3))*4
                 + (r16 >> 3) + ((i >> 2) << 1);
        bSlot[i] = ((nt*2 + kc)*32 + (n8 << 2) + (i & 3))*2 + (i >> 2);
    }

    float acc[4][4][4];
#pragma unroll
    for (int a = 0; a < 4; a++)
#pragma unroll
        for (int b = 0; b < 4; b++)
#pragma unroll
            for (int c = 0; c < 4; c++) acc[a][b][c] = 0.f;

    const int nTiles = kLen >> 4;

    // prime buffer 0
    {
        float4 a0 = *(const float4*)(Aptr);
        float4 a1 = *(const float4*)(Aptr + 4);
        float4 b0 = *(const float4*)(Bptr);
        float4 b1 = *(const float4*)(Bptr + 4);
        float av[8] = {a0.x,a0.y,a0.z,a0.w,a1.x,a1.y,a1.z,a1.w};
        float bv[8] = {b0.x,b0.y,b0.z,b0.w,b1.x,b1.y,b1.z,b1.w};
#pragma unroll
        for (int s = 0; s < 8; s++) {
            const int i = (s + rot) & 7;
            As[0][aSlot[i]] = to_tf32(av[i]);
            Bs[0][bSlot[i]] = to_tf32(bv[i]);
        }
    }
    __syncthreads();

    int buf = 0;
    for (int t = 0; t < nTiles; t++) {
        const bool has = (t + 1) < nTiles;
        float4 na0, na1, nb0, nb1;
        if (has) {
            const int ko = (t + 1) << 4;
            na0 = *(const float4*)(Aptr + ko);
            na1 = *(const float4*)(Aptr + ko + 4);
            nb0 = *(const float4*)(Bptr + ko);
            nb1 = *(const float4*)(Bptr + ko + 4);
        }

        // compute on fragment-packed As/Bs[buf]
#pragma unroll
        for (int kk = 0; kk < 2; kk++) {
            unsigned ar[4][4], br[4][2];
#pragma unroll
            for (int mi = 0; mi < 4; mi++) {
                const float4 af = *(const float4*)
                    &As[buf][(((wm*4 + mi)*2 + kk)*32 + lane)*4];
                ar[mi][0] = __float_as_uint(af.x);
                ar[mi][1] = __float_as_uint(af.y);
                ar[mi][2] = __float_as_uint(af.z);
                ar[mi][3] = __float_as_uint(af.w);
            }
#pragma unroll
            for (int ni = 0; ni < 4; ni++) {
                const float2 bf = *(const float2*)
                    &Bs[buf][(((wn*4 + ni)*2 + kk)*32 + lane)*2];
                br[ni][0] = __float_as_uint(bf.x);
                br[ni][1] = __float_as_uint(bf.y);
            }
#pragma unroll
            for (int mi = 0; mi < 4; mi++)
#pragma unroll
                for (int ni = 0; ni < 4; ni++)
                    MMA_TF32(acc[mi][ni], ar[mi], br[ni]);
        }

        if (has) {
            const int nb = buf ^ 1;
            float av[8] = {na0.x,na0.y,na0.z,na0.w,na1.x,na1.y,na1.z,na1.w};
            float bv[8] = {nb0.x,nb0.y,nb0.z,nb0.w,nb1.x,nb1.y,nb1.z,nb1.w};
#pragma unroll
            for (int s = 0; s < 8; s++) {
                const int i = (s + rot) & 7;
                As[nb][aSlot[i]] = to_tf32(av[i]);
                Bs[nb][bSlot[i]] = to_tf32(bv[i]);
            }
            __syncthreads();
            buf = nb;
        }
    }

    // epilogue
    float* Cz = C + (size_t)z * cStrideZ;
#pragma unroll
    for (int mi = 0; mi < 4; mi++) {
        const int row = m0 + wm*64 + mi*16 + (lane >> 2);
#pragma unroll
        for (int ni = 0; ni < 4; ni++) {
            const int col = n0 + wn*32 + ni*8 + 2*(lane & 3);
            const float bv0 = bias ? bias[col]     : 0.f;
            const float bv1 = bias ? bias[col + 1] : 0.f;
            float v0 = acc[mi][ni][0] + bv0;
            float v1 = acc[mi][ni][1] + bv1;
            float v2 = acc[mi][ni][2] + bv0;
            float v3 = acc[mi][ni][3] + bv1;
            if (doRelu) {
                v0 = fmaxf(v0, 0.f); v1 = fmaxf(v1, 0.f);
                v2 = fmaxf(v2, 0.f); v3 = fmaxf(v3, 0.f);
            }
            if (row < M)
                *(float2*)&Cz[(size_t)row * N + col]       = make_float2(v0, v1);
            if (row + 8 < M)
                *(float2*)&Cz[(size_t)(row + 8) * N + col] = make_float2(v2, v3);
        }
    }
}

// ---------------------------------------------------------------------------
// Layer-0 attention from cached QKV0 [t][b][768]; last token's QKV = bias.
// ---------------------------------------------------------------------------
__global__ __launch_bounds__(128) void attn0_kernel(
    const float* __restrict__ QKV0, const float* __restrict__ qkvb,
    float* __restrict__ out, int T)
{
    const int b = blockIdx.x >> 2, h = blockIdx.x & 3;
    const int tid = threadIdx.x, lane = tid & 31, w = tid >> 5;

    __shared__ float Kt[64*33];
    __shared__ float Vs[32*64];
    __shared__ float Qs[4][64];

    for (int idx = tid; idx < T*64; idx += 128) {
        const int s = idx >> 6, d = idx & 63;
        if (s == T-1) {
            Kt[d*33 + s] = qkvb[256 + h*64 + d];
            Vs[s*64 + d] = qkvb[512 + h*64 + d];
        } else {
            const float* p = QKV0 + ((size_t)s * B_ + b) * 768;
            Kt[d*33 + s] = p[256 + h*64 + d];
            Vs[s*64 + d] = p[512 + h*64 + d];
        }
    }
    __syncthreads();

    for (int t = w; t < T; t += 4) {
        const float* qsrc = (t == T-1) ? (qkvb + h*64)
                                       : (QKV0 + ((size_t)t * B_ + b) * 768 + h*64);
        float* Qrow = Qs[w];
        Qrow[lane]      = qsrc[lane];
        Qrow[lane + 32] = qsrc[lane + 32];
        __syncwarp();
        float sc;
        if (lane < T) {
            float s = 0.f;
#pragma unroll
            for (int d = 0; d < 64; d++) s += Qrow[d] * Kt[d*33 + lane];
            sc = s * 0.125f;
        } else sc = -3.4e38f;
        float m = sc;
#pragma unroll
        for (int o = 16; o > 0; o >>= 1) m = fmaxf(m, __shfl_xor_sync(0xffffffffu, m, o));
        float p = expf(sc - m);
        float sum = p;
#pragma unroll
        for (int o = 16; o > 0; o >>= 1) sum += __shfl_xor_sync(0xffffffffu, sum, o);
        float inv = 1.f / sum;
        float o0 = 0.f, o1 = 0.f;
        for (int s = 0; s < T; s++) {
            float ps = __shfl_sync(0xffffffffu, p, s);
            o0 += ps * Vs[s*64 + lane];
            o1 += ps * Vs[s*64 + 32 + lane];
        }
        float* op = out + ((size_t)b * T + t) * D_H_ + h*64;
        op[lane]      = o0 * inv;
        op[lane + 32] = o1 * inv;
        __syncwarp();
    }
}

// ---------------------------------------------------------------------------
// Layer-1 attention: K/V from KVB [b][t][512]; Q summed from 4 split-K
// partials (Qp[z*pStride + b*256 + ...]) plus bias. Last query only.
// ---------------------------------------------------------------------------
__global__ __launch_bounds__(128) void attn1_kernel(
    const float* __restrict__ KVB, const float* __restrict__ Qp, int pStride,
    const float* __restrict__ qbias, float* __restrict__ out, int T)
{
    const int b = blockIdx.x >> 2, h = blockIdx.x & 3;
    const int tid = threadIdx.x, lane = tid & 31, w = tid >> 5;

    __shared__ float Kt[64*33];
    __shared__ float Vs[32*64];
    __shared__ float Qs[64];

    const float* base = KVB + (size_t)b * T * 512;
    for (int idx = tid; idx < T*64; idx += 128) {
        const int s = idx >> 6, d = idx & 63;
        Kt[d*33 + s] = base[(size_t)s*512 + h*64 + d];
        Vs[s*64 + d] = base[(size_t)s*512 + 256 + h*64 + d];
    }
    __syncthreads();

    if (w == 0) {
        const size_t qi = (size_t)b * 256 + h*64;
#pragma unroll
        for (int half = 0; half < 2; half++) {
            const size_t i = qi + half*32 + lane;
            Qs[half*32 + lane] = qbias[h*64 + half*32 + lane]
                + Qp[i] + Qp[(size_t)pStride + i]
                + Qp[2*(size_t)pStride + i] + Qp[3*(size_t)pStride + i];
        }
        __syncwarp();
        float sc;
        if (lane < T) {
            float s = 0.f;
#pragma unroll
            for (int d = 0; d < 64; d++) s += Qs[d] * Kt[d*33 + lane];
            sc = s * 0.125f;
        } else sc = -3.4e38f;
        float m = sc;
#pragma unroll
        for (int o = 16; o > 0; o >>= 1) m = fmaxf(m, __shfl_xor_sync(0xffffffffu, m, o));
        float p = expf(sc - m);
        float sum = p;
#pragma unroll
        for (int o = 16; o > 0; o >>= 1) sum += __shfl_xor_sync(0xffffffffu, sum, o);
        float inv = 1.f / sum;
        float o0 = 0.f, o1 = 0.f;
        for (int s = 0; s < T; s++) {
            float ps = __shfl_sync(0xffffffffu, p, s);
            o0 += ps * Vs[s*64 + lane];
            o1 += ps * Vs[s*64 + 32 + lane];
        }
        float* op = out + (size_t)b * D_H_ + h*64;
        op[lane]      = o0 * inv;
        op[lane + 32] = o1 * inv;
    }
}

// ---------------------------------------------------------------------------
// LayerNorm cores
// ---------------------------------------------------------------------------
__device__ __forceinline__ void ln_core(float v, float* dst, int d,
                                        const float* gamma, const float* beta)
{
    __shared__ float s1[8], s2[8];
    float sum = v, sq = v*v;
#pragma unroll
    for (int o = 16; o > 0; o >>= 1) {
        sum += __shfl_down_sync(0xffffffffu, sum, o);
        sq  += __shfl_down_sync(0xffffffffu, sq,  o);
    }
    const int wrp = d >> 5, lane = d & 31;
    if (lane == 0) { s1[wrp] = sum; s2[wrp] = sq; }
    __syncthreads();
    if (wrp == 0) {
        float a = (lane < 8) ? s1[lane] : 0.f;
        float c = (lane < 8) ? s2[lane] : 0.f;
#pragma unroll
        for (int o = 4; o > 0; o >>= 1) {
            a += __shfl_down_sync(0xffffffffu, a, o);
            c += __shfl_down_sync(0xffffffffu, c, o);
        }
        if (lane == 0) { s1[0] = a; s2[0] = c; }
    }
    __syncthreads();
    const float mean = s1[0] * (1.f/256.f);
    const float var  = s2[0] * (1.f/256.f) - mean*mean;
    const float r = rsqrtf(var + 1e-5f);
    dst[d] = (v - mean) * r * gamma[d] + beta[d];
}

// dst[row] = LN(resid[(row*rStride+rOff)] + Σ_z parts + dbias)
__global__ __launch_bounds__(256) void add_ln_p4(
    float* __restrict__ dst, const float* __restrict__ resid,
    int rStride, int rOff,
    const float* __restrict__ parts, int pStride,
    const float* __restrict__ dbias,
    const float* __restrict__ gamma, const float* __restrict__ beta)
{
    const int row = blockIdx.x, d = threadIdx.x;
    const size_t i = (size_t)row * D_H_ + d;
    float v = resid[((size_t)row * rStride + rOff) * D_H_ + d] + dbias[d]
            + parts[i] + parts[(size_t)pStride + i]
            + parts[2*(size_t)pStride + i] + parts[3*(size_t)pStride + i];
    ln_core(v, dst + (size_t)row * D_H_, d, gamma, beta);
}

// resid from MEMB [t][b][256] (zero for t == T-1); delta = 4 partials + bias
__global__ __launch_bounds__(256) void add_ln_mem_p4(
    float* __restrict__ dst, const float* __restrict__ MEMB,
    const float* __restrict__ parts, int pStride,
    const float* __restrict__ dbias,
    const float* __restrict__ gamma, const float* __restrict__ beta, int T)
{
    const int row = blockIdx.x, d = threadIdx.x;
    const int t = row % T, b = row / T;
    const size_t i = (size_t)row * D_H_ + d;
    float v = dbias[d]
            + parts[i] + parts[(size_t)pStride + i]
            + parts[2*(size_t)pStride + i] + parts[3*(size_t)pStride + i];
    if (t < T-1) v += MEMB[((size_t)t * B_ + b) * D_H_ + d];
    ln_core(v, dst + (size_t)row * D_H_, d, gamma, beta);
}

// ---------------------------------------------------------------------------
// Generic split-K reduce: dst = Σ_z parts (+bias) (ReLU opt). float4 vectorized.
// ---------------------------------------------------------------------------
__global__ void reduce4(float* __restrict__ dst, const float* __restrict__ parts,
                        int pStride, const float* __restrict__ bias,
                        int total4, int cols4, int doRelu)
{
    int i4 = blockIdx.x * 256 + threadIdx.x;
    if (i4 >= total4) return;
    const float4* p0 = (const float4*)parts + i4;
    float4 a = p0[0];
    float4 b = *((const float4*)(parts + (size_t)pStride) + i4);
    float4 c = *((const float4*)(parts + 2*(size_t)pStride) + i4);
    float4 d = *((const float4*)(parts + 3*(size_t)pStride) + i4);
    float4 v = make_float4(a.x+b.x+c.x+d.x, a.y+b.y+c.y+d.y,
                           a.z+b.z+c.z+d.z, a.w+b.w+c.w+d.w);
    if (bias) {
        const float4 bb = *((const float4*)bias + (i4 % cols4));
        v.x += bb.x; v.y += bb.y; v.z += bb.z; v.w += bb.w;
    }
    if (doRelu) {
        v.x = fmaxf(v.x, 0.f); v.y = fmaxf(v.y, 0.f);
        v.z = fmaxf(v.z, 0.f); v.w = fmaxf(v.w, 0.f);
    }
    ((float4*)dst)[i4] = v;
}

// ---------------------------------------------------------------------------
// Glue kernels
// ---------------------------------------------------------------------------
__global__ void build_spkcat(float* __restrict__ SC, const float* __restrict__ POOLED,
                             const float* __restrict__ x, int j)
{
    int i = blockIdx.x * 256 + threadIdx.x;
    if (i >= 64 * 1536) return;
    int g = i / 1536, c = i % 1536;
    SC[i] = (c < 768) ? POOLED[(size_t)(g*8) * 768 + c]
                      : x[(size_t)((g*32 + j) * 8) * 768 + (c - 768)];
}

__global__ void build_xj(float* __restrict__ XJ, const float* __restrict__ POOLED,
                         const float* __restrict__ SPK, const float* __restrict__ x,
                         int j, int first)
{
    int i = blockIdx.x * 256 + threadIdx.x;
    if (i >= B_ * 768) return;
    int b = i / 768, c = i % 768;
    int g = b >> 3, p = b & 7;
    float v;
    if (first)       v = x[(size_t)((g*32 + j) * 8 + p) * 768 + c];
    else if (p == 0) v = SPK[(size_t)g * 768 + c];
    else             v = POOLED[(size_t)b * 768 + c];
    XJ[i] = v;
}

__global__ __launch_bounds__(256) void gat_finish(
    float* __restrict__ MEMj, const float* __restrict__ HG,
    const float* __restrict__ a_src, const float* __restrict__ a_dst,
    const float* __restrict__ gat_b)
{
    int g = blockIdx.x;
    int tid = threadIdx.x, lane = tid & 31, w = tid >> 5;
    __shared__ float sES[8][4], sED[8][4];
    const float* hgBase = HG + (size_t)g * 8 * 1024;

    {
        int p = w;
        const float* hp = hgBase + (size_t)p * 1024;
        for (int h = 0; h < 4; h++) {
            float s1 = 0.f, s2 = 0.f;
            const float* hr  = hp + h*256;
            const float* asr = a_src + h*256;
            const float* adr = a_dst + h*256;
            for (int d = lane; d < 256; d += 32) {
                float hv = hr[d];
                s1 += hv * asr[d];
                s2 += hv * adr[d];
            }
#pragma unroll
            for (int o = 16; o > 0; o >>= 1) {
                s1 += __shfl_down_sync(0xffffffffu, s1, o);
                s2 += __shfl_down_sync(0xffffffffu, s2, o);
            }
            if (lane == 0) { sES[p][h] = s1; sED[p][h] = s2; }
        }
    }
    __syncthreads();

    int o = tid;
    for (int d = 0; d < 8; d++) {
        float val = 0.f;
        if (d == 0) {
#pragma unroll
            for (int h = 0; h < 4; h++)
                val += hgBase[h*256 + o];
        } else {
#pragma unroll
            for (int h = 0; h < 4; h++) {
                float e0 = sES[0][h] + sED[d][h];
                float e1 = sES[d][h] + sED[d][h];
                e0 = (e0 > 0.f) ? e0 : 0.2f*e0;
                e1 = (e1 > 0.f) ? e1 : 0.2f*e1;
                float m  = fmaxf(e0, e1);
                float w0 = expf(e0 - m), w1 = expf(e1 - m);
                float inv = 1.f / (w0 + w1);
                val += (w0 * hgBase[h*256 + o] +
                        w1 * hgBase[(size_t)d*1024 + h*256 + o]) * inv;
            }
        }
        MEMj[(size_t)(g*8 + d) * D_H_ + o] = 0.25f * val + gat_b[o];
    }
}

__global__ __launch_bounds__(32) void cls_out(
    float* __restrict__ out, const float* __restrict__ MEMB,
    const float* __restrict__ w, const float* __restrict__ bias)
{
    int r = blockIdx.x;
    int lane = threadIdx.x;
    int g = r >> 5, s = r & 31;
    const float* v = MEMB + ((size_t)s * B_ + g*8) * D_H_;
    for (int c = 0; c < 7; c++) {
        float sum = 0.f;
        for (int d = lane; d < 256; d += 32) sum += v[d] * w[c*256 + d];
#pragma unroll
        for (int o = 16; o > 0; o >>= 1) sum += __shfl_down_sync(0xffffffffu, sum, o);
        if (lane == 0) out[(size_t)r*7 + c] = sum + bias[c];
    }
}

// ---------------------------------------------------------------------------
// Host orchestration
// ---------------------------------------------------------------------------
static inline void gemm_tc(float* C, const float* A, const float* Bw, const float* bias,
                           int M, int N, int K, int lda, int relu)
{
    dim3 grid(N / 128, (M + 127) / 128, 1);
    sgemm_tf32_nt<<<grid, 256>>>(A, Bw, C, bias, M, N, K, lda, K, relu, 0);
}

// split-K x4: partials to Cpart[z], bias deferred to the reducing consumer
static inline void gemm_tc_sk4(float* Cpart, const float* A, const float* Bw,
                               int M, int N, int K, int lda, int pStride)
{
    dim3 grid(N / 128, (M + 127) / 128, 4);
    sgemm_tf32_nt<<<grid, 256>>>(A, Bw, Cpart, nullptr, M, N, K/4, lda, K, 0, pStride);
}

static inline void red4(float* dst, const float* parts, int pStride,
                        const float* bias, int rows, int cols, int relu)
{
    int total4 = rows * cols / 4;
    reduce4<<<(total4 + 255)/256, 256>>>(dst, parts, pStride, bias,
                                         total4, cols/4, relu);
}

extern "C" void kernel_launch(void* const* d_in, const int* in_sizes, int n_in,
                              void* d_out, int out_size)
{
    (void)in_sizes; (void)n_in; (void)out_size;

    const float* x      = (const float*)d_in[0];
    const float* gat_w  = (const float*)d_in[3];
    const float* a_src  = (const float*)d_in[4];
    const float* a_dst  = (const float*)d_in[5];
    const float* gat_b  = (const float*)d_in[6];
    const float* qkv_w  = (const float*)d_in[7];
    const float* qkv_b  = (const float*)d_in[8];
    const float* out_w  = (const float*)d_in[9];
    const float* out_b  = (const float*)d_in[10];
    const float* ln1_g  = (const float*)d_in[11];
    const float* ln1_b  = (const float*)d_in[12];
    const float* ff1_w  = (const float*)d_in[13];
    const float* ff1_b  = (const float*)d_in[14];
    const float* ff2_w  = (const float*)d_in[15];
    const float* ff2_b  = (const float*)d_in[16];
    const float* ln2_g  = (const float*)d_in[17];
    const float* ln2_b  = (const float*)d_in[18];
    const float* proj_w = (const float*)d_in[19];
    const float* proj_b = (const float*)d_in[20];
    const float* spk_w  = (const float*)d_in[21];
    const float* spk_b  = (const float*)d_in[22];
    const float* cls_w  = (const float*)d_in[23];
    const float* cls_b  = (const float*)d_in[24];

    float* pool = nullptr;
    cudaGetSymbolAddress((void**)&pool, g_pool);

    float* QKV0   = pool + OFF_QKV0;
    float* H      = pool + OFF_H;
    float* AO     = pool + OFF_AO;
    float* FFB    = pool + OFF_FFB;
    float* KVB    = pool + OFF_KVB;
    float* MEMB   = pool + OFF_MEM;
    float* XJ     = pool + OFF_XJ;
    float* POOLED = pool + OFF_POOLED;
    float* HG     = pool + OFF_HG;
    float* SC     = pool + OFF_SC;
    float* SPK    = pool + OFF_SPK;
    float* C_ATT  = pool + OFF_CATT;
    float* C_H    = pool + OFF_CH;
    float* C_T1   = pool + OFF_CT1;
    float* P4     = pool + OFF_P4;

    const float* qkv_w1 = qkv_w + 768*256;
    const float* qkv_b1 = qkv_b + 768;

    for (int j = 0; j < S_; j++) {
        if (j > 0) {
            const int T  = j + 1;
            const int NT = B_ * T;

            // ---- layer 0 (QKV cached in QKV0; zero-token QKV == bias) ----
            attn0_kernel<<<B_*NH_T_, 128>>>(QKV0, qkv_b, AO, T);
            gemm_tc_sk4(P4, AO, out_w, NT, 256, 256, 256, NT*256);
            add_ln_mem_p4<<<NT, 256>>>(H, MEMB, P4, NT*256, out_b, ln1_g, ln1_b, T);
            gemm_tc(FFB, H, ff1_w, ff1_b, NT, 2048, 256, 256, 1);
            gemm_tc_sk4(P4, FFB, ff2_w, NT, 256, 2048, 2048, NT*256);
            add_ln_p4<<<NT, 256>>>(H, H, 1, 0, P4, NT*256, ff2_b, ln2_g, ln2_b);

            // ---- layer 1: K/V for all tokens, Q for last tokens only ----
            gemm_tc(KVB, H, qkv_w1 + 256*256, qkv_b1 + 256, NT, 512, 256, 256, 0);
            gemm_tc_sk4(P4, H + (size_t)(T-1)*256, qkv_w1, 512, 256, 256, T*256, 512*256);
            attn1_kernel<<<B_*NH_T_, 128>>>(KVB, P4, 512*256, qkv_b1, C_ATT, T);
            gemm_tc_sk4(P4, C_ATT, out_w + 256*256, 512, 256, 256, 256, 512*256);
            add_ln_p4<<<B_, 256>>>(C_H, H, T, T-1, P4, 512*256, out_b + 256,
                                   ln1_g + 256, ln1_b + 256);
            gemm_tc_sk4(P4, C_H, ff1_w + 2048*256, 512, 2048, 256, 256, 512*2048);
            red4(C_T1, P4, 512*2048, ff1_b + 2048, 512, 2048, 1);
            gemm_tc_sk4(P4, C_T1, ff2_w + 256*2048, 512, 256, 2048, 2048, 512*256);
            add_ln_p4<<<B_, 256>>>(C_H, C_H, 1, 0, P4, 512*256, ff2_b + 256,
                                   ln2_g + 256, ln2_b + 256);

            // ---- pooled projection + speaker path ----
            gemm_tc(POOLED, C_H, proj_w, proj_b, 512, 768, 256, 256, 0);
            build_spkcat<<<(64*1536 + 255)/256, 256>>>(SC, POOLED, x, j);
            gemm_tc_sk4(P4, SC, spk_w, 64, 768, 1536, 1536, 64*768);
            red4(SPK, P4, 64*768, spk_b, 64, 768, 1);
            build_xj<<<(B_*768 + 255)/256, 256>>>(XJ, POOLED, SPK, x, j, 0);
        } else {
            build_xj<<<(B_*768 + 255)/256, 256>>>(XJ, POOLED, SPK, x, 0, 1);
        }

        // ---- GAT (HG split-K over K=768 -> 12 iters instead of 48) ----
        gemm_tc_sk4(P4, XJ, gat_w, 512, 1024, 768, 768, 512*1024);
        red4(HG, P4, 512*1024, nullptr, 512, 1024, 0);
        gat_finish<<<G_, 256>>>(MEMB + (size_t)j * B_ * D_H_, HG, a_src, a_dst, gat_b);

        // ---- cache layer-0 QKV of the new memory row (used by later steps) ----
        if (j < S_ - 1) {
            gemm_tc_sk4(P4, MEMB + (size_t)j * B_ * D_H_, qkv_w, 512, 768, 256, 256,
                        512*768);
            red4(QKV0 + (size_t)j * B_ * 768, P4, 512*768, qkv_b, 512, 768, 0);
        }
    }

    cls_out<<<G_*S_, 32>>>((float*)d_out, MEMB, cls_w, cls_b);
}